// round 12
// baseline (speedup 1.0000x reference)
#include <cuda_runtime.h>
#include <cuda_bf16.h>
#include <cstdint>
#include <cstddef>

#define BB 32
#define CC 256
#define HWD 4096
#define RR 64
#define SINK_IT 6

__device__ float g_pooled[BB*CC];
__device__ float g_h[BB*RR];
__device__ __nv_bfloat16 g_K0[(size_t)BB*CC*CC];
__device__ uint8_t g_M8[(size_t)BB*CC*CC];        // e4m3, M*64
__device__ uint8_t g_x8[(size_t)BB*HWD*CC];       // e4m3 x^T

__device__ __forceinline__ uint32_t s2u(const void* p) {
  return (uint32_t)__cvta_generic_to_shared(p);
}
__device__ __forceinline__ void cp16(uint32_t d, const void* s) {
  asm volatile("cp.async.cg.shared.global [%0], [%1], 16;" :: "r"(d), "l"(s));
}
__device__ __forceinline__ uint32_t fp8x2(float lo, float hi) {
  uint16_t r;
  asm("cvt.rn.satfinite.e4m3x2.f32 %0, %1, %2;" : "=h"(r) : "f"(hi), "f"(lo));
  return (uint32_t)r;
}

// ===== K1: transpose x -> e4m3 x8, pooled partials. Full tile resident, 1 sync
#define SMEM_POOL (256*68*4)
__global__ void __launch_bounds__(256) k_poolT(const float* __restrict__ x) {
  extern __shared__ float ts[];   // 256 rows x 68 pitch
  const int b = blockIdx.y, n0 = blockIdx.x * 64, t = threadIdx.x;
  const int rl = t >> 2, c4 = t & 3;
  const int nw = t & 63, cwq = (t >> 6) * 16;
  #pragma unroll
  for (int cg = 0; cg < 4; cg++) {
    int ch = cg*64 + rl;
    const float4* src = (const float4*)(x + ((size_t)b*CC + ch)*HWD + n0 + c4*16);
    float4 a = src[0], bq = src[1], cq = src[2], dq = src[3];
    float4* tr = (float4*)(ts + ch*68 + c4*16);
    tr[0]=a; tr[1]=bq; tr[2]=cq; tr[3]=dq;
    float s = (a.x+a.y+a.z+a.w) + (bq.x+bq.y+bq.z+bq.w)
            + (cq.x+cq.y+cq.z+cq.w) + (dq.x+dq.y+dq.z+dq.w);
    s += __shfl_xor_sync(0xffffffffu, s, 1);
    s += __shfl_xor_sync(0xffffffffu, s, 2);
    if (c4 == 0) atomicAdd(&g_pooled[b*CC + ch], s);
  }
  __syncthreads();
  #pragma unroll
  for (int cg = 0; cg < 4; cg++) {
    int cbase = cg*64 + cwq;
    uint32_t pk[4];
    #pragma unroll
    for (int i = 0; i < 4; i++) {
      float v0 = ts[(cbase + 4*i + 0)*68 + nw];
      float v1 = ts[(cbase + 4*i + 1)*68 + nw];
      float v2 = ts[(cbase + 4*i + 2)*68 + nw];
      float v3 = ts[(cbase + 4*i + 3)*68 + nw];
      pk[i] = fp8x2(v0, v1) | (fp8x2(v2, v3) << 16);
    }
    uint8_t* dst = g_x8 + ((size_t)b*HWD + n0 + nw)*CC + cbase;
    *(uint4*)dst = make_uint4(pk[0], pk[1], pk[2], pk[3]);
  }
}

// ============ K2: h = silu(mean @ w1^T + b1); zero pooled for next replay ===
__global__ void k_fc1(const float* __restrict__ w1, const float* __restrict__ b1) {
  int b = blockIdx.x, r = threadIdx.x;
  __shared__ float p[CC];
  for (int k = r; k < CC; k += RR) p[k] = g_pooled[b*CC + k] * (1.0f/4096.0f);
  __syncthreads();
  for (int k = r; k < CC; k += RR) g_pooled[b*CC + k] = 0.f;
  const float4* wr = (const float4*)(w1 + (size_t)r * CC);
  float acc = b1[r];
  #pragma unroll 8
  for (int k = 0; k < 64; k++) {
    float4 w = wr[k];
    acc += w.x*p[4*k] + w.y*p[4*k+1] + w.z*p[4*k+2] + w.w*p[4*k+3];
  }
  g_h[b*RR + r] = acc / (1.0f + __expf(-acc));
}

// ============ K3: weights -> exp(w - rowmax) -> K0; batch-split grid ========
__global__ void __launch_bounds__(256) k_fc2_exp(const float* __restrict__ w2,
                                                 const float* __restrict__ b2) {
  const int i = blockIdx.x, j = threadIdx.x;
  const int b0 = blockIdx.y * 16;
  const int w = j >> 5, l = j & 31;
  __shared__ float hs[16*RR];
  __shared__ float red[8*16];
  for (int tt = j; tt < 16*RR; tt += 256) hs[tt] = g_h[b0*RR + tt];
  __syncthreads();

  const float4* w2r = (const float4*)(w2 + (size_t)(i*CC + j) * RR);
  const float bv = b2[i*CC + j];
  float acc[16];
  #pragma unroll
  for (int b = 0; b < 16; b++) acc[b] = bv;
  #pragma unroll
  for (int k4 = 0; k4 < 16; k4++) {
    float4 wv = w2r[k4];
    #pragma unroll
    for (int b = 0; b < 16; b++) {
      const float* hb = hs + b*64 + k4*4;
      acc[b] += wv.x*hb[0] + wv.y*hb[1] + wv.z*hb[2] + wv.w*hb[3];
    }
  }
  #pragma unroll
  for (int b = 0; b < 16; b++) {
    float m = acc[b];
    #pragma unroll
    for (int o = 16; o; o >>= 1) m = fmaxf(m, __shfl_xor_sync(0xffffffffu, m, o));
    if (l == b) red[w*16 + b] = m;
  }
  __syncthreads();
  #pragma unroll
  for (int b = 0; b < 16; b++) {
    float bm = red[b];
    #pragma unroll
    for (int ww = 1; ww < 8; ww++) bm = fmaxf(bm, red[ww*16 + b]);
    float e = __expf(acc[b] - bm);
    float eo = __shfl_down_sync(0xffffffffu, e, 1);
    if ((j & 1) == 0) {
      __nv_bfloat162 pk;
      pk.x = __float2bfloat16(e); pk.y = __float2bfloat16(eo);
      *(__nv_bfloat162*)(g_K0 + ((size_t)((b0 + b)*CC + i))*CC + j) = pk;
    }
  }
}

// ============ K4: Sinkhorn u/v scaling form, HFMA2, 6 iters ============
#define KP 264
#define SMEM_SINK (256*KP*2 + 8*256*4 + 256*4 + 256*4 + 256*4 + 128*4)
__global__ void __launch_bounds__(1024, 1) k_sinkhorn() {
  extern __shared__ char smC[];
  __nv_bfloat16* Kb = (__nv_bfloat16*)smC;
  float* red = (float*)(smC + 256*KP*2);
  float* u = red + 8*256;
  float* v = u + 256;
  uint32_t* ub2 = (uint32_t*)(v + 256);
  uint32_t* vb2 = ub2 + 256;
  const int b = blockIdx.x, t = threadIdx.x;
  const __nv_bfloat16* src = g_K0 + (size_t)b * (CC*CC);
  #pragma unroll
  for (int i = 0; i < 8; i++) {
    int idx = t + 1024*i;
    int r = idx >> 5, c8 = idx & 31;
    float4 d = *(const float4*)(src + r*CC + c8*8);
    *(float4*)(Kb + r*KP + c8*8) = d;
  }
  if (t < 256) v[t] = 1.0f;
  if (t < 128) vb2[t] = 0x3F803F80u;
  __syncthreads();

  const int rr = t & 255, q = t >> 8;
  const int cp_ = t & 127, rg = t >> 7;
  const __nv_bfloat162 z2 = __floats2bfloat162_rn(0.f, 0.f);

  for (int it = 0; it < SINK_IT; it++) {
    {
      __nv_bfloat162 a8[8];
      #pragma unroll
      for (int a = 0; a < 8; a++) a8[a] = z2;
      const uint4* kp4 = (const uint4*)(Kb + rr*KP + q*64);
      const uint4* vp4 = (const uint4*)(vb2 + q*32);
      #pragma unroll
      for (int i = 0; i < 8; i++) {
        uint4 kk = kp4[i]; uint4 vv = vp4[i];
        const uint32_t* kw = &kk.x; const uint32_t* vw = &vv.x;
        #pragma unroll
        for (int j = 0; j < 4; j++) {
          a8[(i&1)*4+j] = __hfma2(*(const __nv_bfloat162*)&kw[j],
                                  *(const __nv_bfloat162*)&vw[j], a8[(i&1)*4+j]);
        }
      }
      float s = 0.f;
      #pragma unroll
      for (int a = 0; a < 8; a++) {
        float2 f = __bfloat1622float2(a8[a]);
        s += f.x + f.y;
      }
      red[q*256 + rr] = s;
    }
    __syncthreads();
    if (t < 256) {
      float s = red[t] + red[256+t] + red[512+t] + red[768+t];
      float uu = 1.0f / (s + 1e-12f);
      u[t] = uu;
      __nv_bfloat16 ub = __float2bfloat16(uu);
      __nv_bfloat162 up; up.x = ub; up.y = ub;
      ub2[t] = *(uint32_t*)&up;
    }
    __syncthreads();
    {
      __nv_bfloat162 a8[8];
      #pragma unroll
      for (int a = 0; a < 8; a++) a8[a] = z2;
      const __nv_bfloat16* base = Kb + (rg*32)*KP + 2*cp_;
      const uint32_t* up = ub2 + rg*32;
      #pragma unroll
      for (int i = 0; i < 32; i++) {
        uint32_t k2 = *(const uint32_t*)(base + i*KP);
        uint32_t uu = up[i];
        a8[i&7] = __hfma2(*(const __nv_bfloat162*)&k2,
                          *(const __nv_bfloat162*)&uu, a8[i&7]);
      }
      float a0 = 0.f, a1 = 0.f;
      #pragma unroll
      for (int a = 0; a < 8; a++) {
        float2 f = __bfloat1622float2(a8[a]);
        a0 += f.x; a1 += f.y;
      }
      float2 w2v; w2v.x = a0; w2v.y = a1;
      *(float2*)(red + rg*256 + 2*cp_) = w2v;
    }
    __syncthreads();
    if (t < 256) {
      float s = 0.f;
      #pragma unroll
      for (int g = 0; g < 8; g++) s += red[g*256 + t];
      float vv = 1.0f / (s + 1e-12f);
      v[t] = vv;
      float vn = __shfl_xor_sync(0xffffffffu, vv, 1);
      if ((t & 1) == 0) {
        __nv_bfloat162 vp; vp.x = __float2bfloat16(vv); vp.y = __float2bfloat16(vn);
        vb2[t >> 1] = *(uint32_t*)&vp;
      }
    }
    __syncthreads();
  }
  for (int idx = t; idx < 16384; idx += 1024) {
    int i = idx >> 6, c4 = idx & 63;
    float su = 64.0f * u[i];
    const __nv_bfloat16* rp = Kb + i*KP + 4*c4;
    float m0 = su * __bfloat162float(rp[0]) * v[4*c4+0];
    float m1 = su * __bfloat162float(rp[1]) * v[4*c4+1];
    float m2 = su * __bfloat162float(rp[2]) * v[4*c4+2];
    float m3 = su * __bfloat162float(rp[3]) * v[4*c4+3];
    uint32_t pk = fp8x2(m0, m1) | (fp8x2(m2, m3) << 16);
    *(uint32_t*)(g_M8 + (size_t)b*(CC*CC) + i*CC + 4*c4) = pk;
  }
}

// ===== K5: out = x + (scale/64)*M8@x8^T — 512 thr, 32x32 warp tile =========
#define APITCH 80
#define ASTG (128*APITCH)
#define STG (2*ASTG)
#define XPAD (64*512)
#define SMEM_MIX (3*STG + XPAD)
__global__ void __launch_bounds__(512, 2) k_mix(const float* __restrict__ x,
                                               const float* __restrict__ scale,
                                               float* __restrict__ out) {
  extern __shared__ __align__(128) char sm[];
  const int t = threadIdx.x;
  const int m0 = blockIdx.x * 128;
  const int n0 = blockIdx.y * 128;
  const int b  = blockIdx.z;
  const uint32_t s0 = s2u(sm);
  const int w = t >> 5, l = t & 31;
  const int wm = (w & 3) * 32, wn = (w >> 2) * 32;
  const int g = l >> 3, r = l & 7;
  const int lrow = r + (g & 1) * 8;
  const int lchunk = (g >> 1) * 16;

  const uint8_t* Ab = g_M8 + ((size_t)b << 16) + (size_t)m0 * CC;
  const uint8_t* Bb = g_x8 + ((size_t)b << 20) + (size_t)n0 * CC;
  const float* xsrc = x + ((size_t)b*CC + m0)*HWD + n0;

  #define PREFETCH(kc) {                                                        \
    uint32_t As_ = s0 + ((kc) % 3) * STG;                                       \
    uint32_t Bs_ = As_ + ASTG;                                                  \
    { int rw = t >> 2, c_ = t & 3;                                              \
      cp16(As_ + rw*APITCH + c_*16, Ab + (size_t)rw*CC + (kc)*64 + c_*16);      \
      cp16(Bs_ + rw*APITCH + c_*16, Bb + (size_t)rw*CC + (kc)*64 + c_*16); }    \
    asm volatile("cp.async.commit_group;");                                     \
  }
  // x residual rows: 0..31 -> stage1, 32..63 -> stage2, 64..127 -> pad
  #define XLD(base, r0, cnt) {                                                  \
    _Pragma("unroll")                                                           \
    for (int i_ = 0; i_ < (cnt); i_++) {                                        \
      int idx = t + 512*i_; int rr_ = (idx >> 5), c16 = idx & 31;               \
      int rg_ = (r0) + rr_;                                                     \
      cp16(s0 + (base) + (uint32_t)rr_*512 + (uint32_t)((c16*16) ^ ((rg_&7)<<5)),\
           xsrc + (size_t)rg_*HWD + c16*4);                                     \
    }                                                                           \
    asm volatile("cp.async.commit_group;");                                     \
  }
  #define COMPUTE(kc) {                                                         \
    uint32_t Ast = s0 + ((kc) % 3) * STG;                                       \
    uint32_t Bst = Ast + ASTG;                                                  \
    uint32_t abase = Ast + (uint32_t)(wm + lrow)*APITCH + lchunk;               \
    uint32_t bbase = Bst + (uint32_t)(wn + lrow)*APITCH + lchunk;               \
    _Pragma("unroll")                                                           \
    for (int ks = 0; ks < 2; ks++) {                                            \
      uint32_t bfr[4][2];                                                       \
      _Pragma("unroll")                                                         \
      for (int ng = 0; ng < 2; ng++) {                                          \
        uint32_t r0, r1, r2, r3;                                                \
        asm volatile("ldmatrix.sync.aligned.m8n8.x4.shared.b16 {%0,%1,%2,%3}, [%4];" \
                     : "=r"(r0), "=r"(r1), "=r"(r2), "=r"(r3)                   \
                     : "r"(bbase + ng*16*APITCH + ks*32));                      \
        bfr[2*ng][0]=r0; bfr[2*ng+1][0]=r1; bfr[2*ng][1]=r2; bfr[2*ng+1][1]=r3; \
      }                                                                         \
      _Pragma("unroll")                                                         \
      for (int mt = 0; mt < 2; mt++) {                                          \
        uint32_t a0, a1, a2, a3;                                                \
        asm volatile("ldmatrix.sync.aligned.m8n8.x4.shared.b16 {%0,%1,%2,%3}, [%4];" \
                     : "=r"(a0), "=r"(a1), "=r"(a2), "=r"(a3)                   \
                     : "r"(abase + mt*16*APITCH + ks*32));                      \
        _Pragma("unroll")                                                       \
        for (int nt = 0; nt < 4; nt++) {                                        \
          asm volatile("mma.sync.aligned.m16n8k32.row.col.f32.e4m3.e4m3.f32 "   \
                       "{%0,%1,%2,%3}, {%4,%5,%6,%7}, {%8,%9}, {%0,%1,%2,%3};"  \
                       : "+f"(acc[mt][nt][0]), "+f"(acc[mt][nt][1]),            \
                         "+f"(acc[mt][nt][2]), "+f"(acc[mt][nt][3])             \
                       : "r"(a0), "r"(a1), "r"(a2), "r"(a3),                    \
                         "r"(bfr[nt][0]), "r"(bfr[nt][1]));                     \
        }                                                                       \
      }                                                                         \
    }                                                                           \
  }

  float acc[2][4][4];
  #pragma unroll
  for (int mt = 0; mt < 2; mt++)
    #pragma unroll
    for (int nt = 0; nt < 4; nt++)
      #pragma unroll
      for (int qq = 0; qq < 4; qq++) acc[mt][nt][qq] = 0.f;

  PREFETCH(0)                 // c1
  PREFETCH(1)                 // c2
  XLD(3*STG, 64, 4)           // c3: x rows 64..127 -> pad (always free)

  asm volatile("cp.async.wait_group 2;" ::: "memory");  // c1 done
  __syncthreads();
  PREFETCH(2)                 // c4
  COMPUTE(0)

  asm volatile("cp.async.wait_group 2;" ::: "memory");  // c2 done
  __syncthreads();
  PREFETCH(3)                 // c5
  COMPUTE(1)

  asm volatile("cp.async.wait_group 1;" ::: "memory");  // c4 done
  __syncthreads();
  XLD(STG, 0, 2)              // c6: x rows 0..31 -> stage1 (now free)
  COMPUTE(2)

  asm volatile("cp.async.wait_group 1;" ::: "memory");  // c5 done
  __syncthreads();
  XLD(2*STG, 32, 2)           // c7: x rows 32..63 -> stage2 (now free)
  COMPUTE(3)

  asm volatile("cp.async.wait_group 0;" ::: "memory");  // all x arrived
  __syncthreads();

  const float sc = scale[0] * 0.015625f;
  float* ob = out + ((size_t)b*CC + m0)*HWD + n0;
  const int er = l >> 2, ec = 2 * (l & 3);
  #pragma unroll
  for (int mt = 0; mt < 2; mt++) {
    #pragma unroll
    for (int nt = 0; nt < 4; nt++) {
      int row = wm + mt*16 + er;
      int col = wn + nt*8 + ec;
      uint32_t xo1 = (row < 32) ? (uint32_t)(STG + row*512)
                   : (row < 64) ? (uint32_t)(2*STG + (row-32)*512)
                                : (uint32_t)(3*STG + (row-64)*512);
      float2 xv = *(const float2*)(sm + xo1 + (uint32_t)((col*4) ^ ((row&7)<<5)));
      float2 ov; ov.x = xv.x + sc*acc[mt][nt][0]; ov.y = xv.y + sc*acc[mt][nt][1];
      *(float2*)(ob + (size_t)row*HWD + col) = ov;
      int row2 = row + 8;
      uint32_t xo2 = (row2 < 32) ? (uint32_t)(STG + row2*512)
                   : (row2 < 64) ? (uint32_t)(2*STG + (row2-32)*512)
                                 : (uint32_t)(3*STG + (row2-64)*512);
      float2 xv2 = *(const float2*)(sm + xo2 + (uint32_t)((col*4) ^ ((row2&7)<<5)));
      float2 ov2; ov2.x = xv2.x + sc*acc[mt][nt][2]; ov2.y = xv2.y + sc*acc[mt][nt][3];
      *(float2*)(ob + (size_t)row2*HWD + col) = ov2;
    }
  }
}

extern "C" void kernel_launch(void* const* d_in, const int* in_sizes, int n_in,
                              void* d_out, int out_size) {
  const float* x     = (const float*)d_in[0];
  const float* w1    = (const float*)d_in[1];
  const float* b1    = (const float*)d_in[2];
  const float* w2    = (const float*)d_in[3];
  const float* b2    = (const float*)d_in[4];
  const float* scale = (const float*)d_in[5];
  float* out = (float*)d_out;

  cudaFuncSetAttribute(k_poolT, cudaFuncAttributeMaxDynamicSharedMemorySize, SMEM_POOL);
  cudaFuncSetAttribute(k_sinkhorn, cudaFuncAttributeMaxDynamicSharedMemorySize, SMEM_SINK);
  cudaFuncSetAttribute(k_mix, cudaFuncAttributeMaxDynamicSharedMemorySize, SMEM_MIX);

  dim3 gpool(HWD/64, BB);
  k_poolT<<<gpool, 256, SMEM_POOL>>>(x);
  k_fc1<<<BB, RR>>>(w1, b1);
  dim3 gfc2(CC, 2);
  k_fc2_exp<<<gfc2, 256>>>(w2, b2);
  k_sinkhorn<<<BB, 1024, SMEM_SINK>>>();
  dim3 gmix(CC/128, HWD/128, BB);
  k_mix<<<gmix, 512, SMEM_MIX>>>(x, scale, out);
}

// round 14
// speedup vs baseline: 1.2405x; 1.2405x over previous
#include <cuda_runtime.h>
#include <cuda_bf16.h>
#include <cstdint>
#include <cstddef>

#define BB 32
#define CC 256
#define HWD 4096
#define RR 64
#define SINK_IT 6

__device__ float g_pooled[BB*CC];
__device__ float g_h[BB*RR];
__device__ __nv_bfloat16 g_K0[(size_t)BB*CC*CC];
__device__ uint8_t g_M8[(size_t)BB*CC*CC];        // e4m3, M*64
__device__ uint8_t g_x8[(size_t)BB*HWD*CC];       // e4m3 x^T

__device__ __forceinline__ uint32_t s2u(const void* p) {
  return (uint32_t)__cvta_generic_to_shared(p);
}
__device__ __forceinline__ void cp16(uint32_t d, const void* s) {
  asm volatile("cp.async.cg.shared.global [%0], [%1], 16;" :: "r"(d), "l"(s));
}
__device__ __forceinline__ uint32_t fp8x2(float lo, float hi) {
  uint16_t r;
  asm("cvt.rn.satfinite.e4m3x2.f32 %0, %1, %2;" : "=h"(r) : "f"(hi), "f"(lo));
  return (uint32_t)r;
}

// ============ K1: transpose x -> e4m3 x8, partial pooled sums ============
__global__ void __launch_bounds__(256) k_poolT(const float* __restrict__ x) {
  __shared__ float ts[64*68];
  const int b = blockIdx.y, n0 = blockIdx.x * 64, t = threadIdx.x;
  const int rl = t >> 2, c4 = t & 3;
  const int nw = t & 63, cw = (t >> 6) * 16;
  for (int cg = 0; cg < 4; cg++) {
    int ch = cg*64 + rl;
    const float4* src = (const float4*)(x + ((size_t)b*CC + ch)*HWD + n0 + c4*16);
    float4 a = src[0], bq = src[1], cq = src[2], dq = src[3];
    float4* tr = (float4*)(ts + rl*68 + c4*16);
    tr[0]=a; tr[1]=bq; tr[2]=cq; tr[3]=dq;
    float s = (a.x+a.y+a.z+a.w) + (bq.x+bq.y+bq.z+bq.w)
            + (cq.x+cq.y+cq.z+cq.w) + (dq.x+dq.y+dq.z+dq.w);
    s += __shfl_xor_sync(0xffffffffu, s, 1);
    s += __shfl_xor_sync(0xffffffffu, s, 2);
    if (c4 == 0) atomicAdd(&g_pooled[b*CC + ch], s);
    __syncthreads();
    uint32_t pk[4];
    #pragma unroll
    for (int i = 0; i < 4; i++) {
      float v0 = ts[(cw + 4*i + 0)*68 + nw];
      float v1 = ts[(cw + 4*i + 1)*68 + nw];
      float v2 = ts[(cw + 4*i + 2)*68 + nw];
      float v3 = ts[(cw + 4*i + 3)*68 + nw];
      pk[i] = fp8x2(v0, v1) | (fp8x2(v2, v3) << 16);
    }
    uint8_t* dst = g_x8 + ((size_t)b*HWD + n0 + nw)*CC + cg*64 + cw;
    *(uint4*)dst = make_uint4(pk[0], pk[1], pk[2], pk[3]);
    __syncthreads();
  }
}

// ============ K2: h = silu(mean @ w1^T + b1); zero pooled for next replay ===
__global__ void k_fc1(const float* __restrict__ w1, const float* __restrict__ b1) {
  int b = blockIdx.x, r = threadIdx.x;
  __shared__ float p[CC];
  for (int k = r; k < CC; k += RR) p[k] = g_pooled[b*CC + k] * (1.0f/4096.0f);
  __syncthreads();
  for (int k = r; k < CC; k += RR) g_pooled[b*CC + k] = 0.f;
  const float4* wr = (const float4*)(w1 + (size_t)r * CC);
  float acc = b1[r];
  #pragma unroll 8
  for (int k = 0; k < 64; k++) {
    float4 w = wr[k];
    acc += w.x*p[4*k] + w.y*p[4*k+1] + w.z*p[4*k+2] + w.w*p[4*k+3];
  }
  g_h[b*RR + r] = acc / (1.0f + __expf(-acc));
}

// ============ K3: weights -> exp(w - rowmax) -> K0; 8 batches/block ========
__global__ void __launch_bounds__(256) k_fc2_exp(const float* __restrict__ w2,
                                                 const float* __restrict__ b2) {
  const int i = blockIdx.x, j = threadIdx.x;
  const int b0 = blockIdx.y * 8;               // 8 batches per block
  const int w = j >> 5, l = j & 31;
  __shared__ float hs[8*RR];
  __shared__ float red[8*8];
  for (int tt = j; tt < 8*RR; tt += 256) hs[tt] = g_h[b0*RR + tt];
  __syncthreads();

  const float4* w2r = (const float4*)(w2 + (size_t)(i*CC + j) * RR);
  const float bv = b2[i*CC + j];
  float acc[8];
  #pragma unroll
  for (int b = 0; b < 8; b++) acc[b] = bv;
  #pragma unroll
  for (int k4 = 0; k4 < 16; k4++) {
    float4 wv = w2r[k4];
    #pragma unroll
    for (int b = 0; b < 8; b++) {
      const float* hb = hs + b*64 + k4*4;
      acc[b] += wv.x*hb[0] + wv.y*hb[1] + wv.z*hb[2] + wv.w*hb[3];
    }
  }
  #pragma unroll
  for (int b = 0; b < 8; b++) {
    float m = acc[b];
    #pragma unroll
    for (int o = 16; o; o >>= 1) m = fmaxf(m, __shfl_xor_sync(0xffffffffu, m, o));
    if (l == b) red[w*8 + b] = m;
  }
  __syncthreads();
  #pragma unroll
  for (int b = 0; b < 8; b++) {
    float bm = red[b];
    #pragma unroll
    for (int ww = 1; ww < 8; ww++) bm = fmaxf(bm, red[ww*8 + b]);
    float e = __expf(acc[b] - bm);
    float eo = __shfl_down_sync(0xffffffffu, e, 1);
    if ((j & 1) == 0) {
      __nv_bfloat162 pk;
      pk.x = __float2bfloat16(e); pk.y = __float2bfloat16(eo);
      *(__nv_bfloat162*)(g_K0 + ((size_t)((b0 + b)*CC + i))*CC + j) = pk;
    }
  }
}

// ============ K4: Sinkhorn u/v scaling form, HFMA2, 6 iters ============
#define KP 264
#define SMEM_SINK (256*KP*2 + 8*256*4 + 256*4 + 256*4 + 256*4 + 128*4)
__global__ void __launch_bounds__(1024, 1) k_sinkhorn() {
  extern __shared__ char smC[];
  __nv_bfloat16* Kb = (__nv_bfloat16*)smC;
  float* red = (float*)(smC + 256*KP*2);
  float* u = red + 8*256;
  float* v = u + 256;
  uint32_t* ub2 = (uint32_t*)(v + 256);
  uint32_t* vb2 = ub2 + 256;
  const int b = blockIdx.x, t = threadIdx.x;
  const __nv_bfloat16* src = g_K0 + (size_t)b * (CC*CC);
  #pragma unroll
  for (int i = 0; i < 8; i++) {
    int idx = t + 1024*i;
    int r = idx >> 5, c8 = idx & 31;
    float4 d = *(const float4*)(src + r*CC + c8*8);
    *(float4*)(Kb + r*KP + c8*8) = d;
  }
  if (t < 256) v[t] = 1.0f;
  if (t < 128) vb2[t] = 0x3F803F80u;
  __syncthreads();

  const int rr = t & 255, q = t >> 8;
  const int cp_ = t & 127, rg = t >> 7;
  const __nv_bfloat162 z2 = __floats2bfloat162_rn(0.f, 0.f);

  for (int it = 0; it < SINK_IT; it++) {
    {
      __nv_bfloat162 a8[8];
      #pragma unroll
      for (int a = 0; a < 8; a++) a8[a] = z2;
      const uint4* kp4 = (const uint4*)(Kb + rr*KP + q*64);
      const uint4* vp4 = (const uint4*)(vb2 + q*32);
      #pragma unroll
      for (int i = 0; i < 8; i++) {
        uint4 kk = kp4[i]; uint4 vv = vp4[i];
        const uint32_t* kw = &kk.x; const uint32_t* vw = &vv.x;
        #pragma unroll
        for (int j = 0; j < 4; j++) {
          a8[(i&1)*4+j] = __hfma2(*(const __nv_bfloat162*)&kw[j],
                                  *(const __nv_bfloat162*)&vw[j], a8[(i&1)*4+j]);
        }
      }
      float s = 0.f;
      #pragma unroll
      for (int a = 0; a < 8; a++) {
        float2 f = __bfloat1622float2(a8[a]);
        s += f.x + f.y;
      }
      red[q*256 + rr] = s;
    }
    __syncthreads();
    if (t < 256) {
      float s = red[t] + red[256+t] + red[512+t] + red[768+t];
      float uu = 1.0f / (s + 1e-12f);
      u[t] = uu;
      __nv_bfloat16 ub = __float2bfloat16(uu);
      __nv_bfloat162 up; up.x = ub; up.y = ub;
      ub2[t] = *(uint32_t*)&up;
    }
    __syncthreads();
    {
      __nv_bfloat162 a8[8];
      #pragma unroll
      for (int a = 0; a < 8; a++) a8[a] = z2;
      const __nv_bfloat16* base = Kb + (rg*32)*KP + 2*cp_;
      const uint32_t* up = ub2 + rg*32;
      #pragma unroll
      for (int i = 0; i < 32; i++) {
        uint32_t k2 = *(const uint32_t*)(base + i*KP);
        uint32_t uu = up[i];
        a8[i&7] = __hfma2(*(const __nv_bfloat162*)&k2,
                          *(const __nv_bfloat162*)&uu, a8[i&7]);
      }
      float a0 = 0.f, a1 = 0.f;
      #pragma unroll
      for (int a = 0; a < 8; a++) {
        float2 f = __bfloat1622float2(a8[a]);
        a0 += f.x; a1 += f.y;
      }
      float2 w2v; w2v.x = a0; w2v.y = a1;
      *(float2*)(red + rg*256 + 2*cp_) = w2v;
    }
    __syncthreads();
    if (t < 256) {
      float s = 0.f;
      #pragma unroll
      for (int g = 0; g < 8; g++) s += red[g*256 + t];
      float vv = 1.0f / (s + 1e-12f);
      v[t] = vv;
      float vn = __shfl_xor_sync(0xffffffffu, vv, 1);
      if ((t & 1) == 0) {
        __nv_bfloat162 vp; vp.x = __float2bfloat16(vv); vp.y = __float2bfloat16(vn);
        vb2[t >> 1] = *(uint32_t*)&vp;
      }
    }
    __syncthreads();
  }
  for (int idx = t; idx < 16384; idx += 1024) {
    int i = idx >> 6, c4 = idx & 63;
    float su = 64.0f * u[i];
    const __nv_bfloat16* rp = Kb + i*KP + 4*c4;
    float m0 = su * __bfloat162float(rp[0]) * v[4*c4+0];
    float m1 = su * __bfloat162float(rp[1]) * v[4*c4+1];
    float m2 = su * __bfloat162float(rp[2]) * v[4*c4+2];
    float m3 = su * __bfloat162float(rp[3]) * v[4*c4+3];
    uint32_t pk = fp8x2(m0, m1) | (fp8x2(m2, m3) << 16);
    *(uint32_t*)(g_M8 + (size_t)b*(CC*CC) + i*CC + 4*c4) = pk;
  }
}

// ===== K5: out = x + (scale/64)*M8@x8^T — 3-stage pipe + smem x residual ====
#define APITCH 80
#define ASTG (128*APITCH)
#define STG (2*ASTG)
#define XPAD (48*512)
#define SMEM_MIX (3*STG + XPAD)
__global__ void __launch_bounds__(256, 2) k_mix(const float* __restrict__ x,
                                                const float* __restrict__ scale,
                                                float* __restrict__ out) {
  extern __shared__ __align__(128) char sm[];
  const int t = threadIdx.x;
  const int m0 = blockIdx.x * 128;
  const int n0 = blockIdx.y * 128;
  const int b  = blockIdx.z;
  const uint32_t s0 = s2u(sm);
  const int w = t >> 5, l = t & 31;
  const int wm = (w & 1) * 64, wn = (w >> 1) * 32;
  const int g = l >> 3, r = l & 7;
  const int lrow = r + (g & 1) * 8;
  const int lchunk = (g >> 1) * 16;

  const uint8_t* Ab = g_M8 + ((size_t)b << 16) + (size_t)m0 * CC;
  const uint8_t* Bb = g_x8 + ((size_t)b << 20) + (size_t)n0 * CC;
  const float* xsrc = x + ((size_t)b*CC + m0)*HWD + n0;

  #define PREFETCH(kc) {                                                        \
    uint32_t As_ = s0 + ((kc) % 3) * STG;                                       \
    uint32_t Bs_ = As_ + ASTG;                                                  \
    _Pragma("unroll")                                                           \
    for (int i_ = 0; i_ < 2; i_++) {                                            \
      int idx = t + 256*i_; int rw = idx >> 2, c_ = idx & 3;                    \
      cp16(As_ + rw*APITCH + c_*16, Ab + (size_t)rw*CC + (kc)*64 + c_*16);      \
      cp16(Bs_ + rw*APITCH + c_*16, Bb + (size_t)rw*CC + (kc)*64 + c_*16);      \
    }                                                                           \
    asm volatile("cp.async.commit_group;");                                     \
  }
  #define XLD(base, r0, cnt) {                                                  \
    _Pragma("unroll")                                                           \
    for (int i_ = 0; i_ < (cnt); i_++) {                                        \
      int idx = t + 256*i_; int rr_ = (idx >> 5), c16 = idx & 31;               \
      int rg_ = (r0) + rr_;                                                     \
      cp16(s0 + (base) + (uint32_t)rr_*512 + (uint32_t)((c16*16) ^ ((rg_&7)<<5)),\
           xsrc + (size_t)rg_*HWD + c16*4);                                     \
    }                                                                           \
    asm volatile("cp.async.commit_group;");                                     \
  }
  #define COMPUTE(kc) {                                                         \
    uint32_t Ast = s0 + ((kc) % 3) * STG;                                       \
    uint32_t Bst = Ast + ASTG;                                                  \
    uint32_t abase = Ast + (uint32_t)(wm + lrow)*APITCH + lchunk;               \
    uint32_t bbase = Bst + (uint32_t)(wn + lrow)*APITCH + lchunk;               \
    _Pragma("unroll")                                                           \
    for (int ks = 0; ks < 2; ks++) {                                            \
      uint32_t bfr[4][2];                                                       \
      _Pragma("unroll")                                                         \
      for (int ng = 0; ng < 2; ng++) {                                          \
        uint32_t r0, r1, r2, r3;                                                \
        asm volatile("ldmatrix.sync.aligned.m8n8.x4.shared.b16 {%0,%1,%2,%3}, [%4];" \
                     : "=r"(r0), "=r"(r1), "=r"(r2), "=r"(r3)                   \
                     : "r"(bbase + ng*16*APITCH + ks*32));                      \
        bfr[2*ng][0]=r0; bfr[2*ng+1][0]=r1; bfr[2*ng][1]=r2; bfr[2*ng+1][1]=r3; \
      }                                                                         \
      _Pragma("unroll")                                                         \
      for (int mt = 0; mt < 4; mt++) {                                          \
        uint32_t a0, a1, a2, a3;                                                \
        asm volatile("ldmatrix.sync.aligned.m8n8.x4.shared.b16 {%0,%1,%2,%3}, [%4];" \
                     : "=r"(a0), "=r"(a1), "=r"(a2), "=r"(a3)                   \
                     : "r"(abase + mt*16*APITCH + ks*32));                      \
        _Pragma("unroll")                                                       \
        for (int nt = 0; nt < 4; nt++) {                                        \
          asm volatile("mma.sync.aligned.m16n8k32.row.col.f32.e4m3.e4m3.f32 "   \
                       "{%0,%1,%2,%3}, {%4,%5,%6,%7}, {%8,%9}, {%0,%1,%2,%3};"  \
                       : "+f"(acc[mt][nt][0]), "+f"(acc[mt][nt][1]),            \
                         "+f"(acc[mt][nt][2]), "+f"(acc[mt][nt][3])             \
                       : "r"(a0), "r"(a1), "r"(a2), "r"(a3),                    \
                         "r"(bfr[nt][0]), "r"(bfr[nt][1]));                     \
        }                                                                       \
      }                                                                         \
    }                                                                           \
  }

  float acc[4][4][4];
  #pragma unroll
  for (int mt = 0; mt < 4; mt++)
    #pragma unroll
    for (int nt = 0; nt < 4; nt++)
      #pragma unroll
      for (int qq = 0; qq < 4; qq++) acc[mt][nt][qq] = 0.f;

  PREFETCH(0)                 // c1
  PREFETCH(1)                 // c2
  XLD(3*STG, 80, 6)           // c3: x rows 80..127 -> pad (always free)

  asm volatile("cp.async.wait_group 2;" ::: "memory");  // c1 done
  __syncthreads();
  PREFETCH(2)                 // c4
  COMPUTE(0)

  asm volatile("cp.async.wait_group 2;" ::: "memory");  // c2 done
  __syncthreads();
  PREFETCH(3)                 // c5
  COMPUTE(1)

  asm volatile("cp.async.wait_group 1;" ::: "memory");  // c4 done
  __syncthreads();
  XLD(STG, 0, 5)              // c6: x rows 0..39 -> stage1 (now free)
  COMPUTE(2)

  asm volatile("cp.async.wait_group 1;" ::: "memory");  // c5 done
  __syncthreads();
  XLD(2*STG, 40, 5)           // c7: x rows 40..79 -> stage2 (now free)
  COMPUTE(3)

  asm volatile("cp.async.wait_group 0;" ::: "memory");  // all x arrived
  __syncthreads();

  const float sc = scale[0] * 0.015625f;
  float* ob = out + ((size_t)b*CC + m0)*HWD + n0;
  const int er = l >> 2, ec = 2 * (l & 3);
  #pragma unroll
  for (int mt = 0; mt < 4; mt++) {
    #pragma unroll
    for (int nt = 0; nt < 4; nt++) {
      int row = wm + mt*16 + er;
      int col = wn + nt*8 + ec;
      uint32_t xo1 = (row < 40) ? (uint32_t)(STG + row*512)
                   : (row < 80) ? (uint32_t)(2*STG + (row-40)*512)
                                : (uint32_t)(3*STG + (row-80)*512);
      float2 xv = *(const float2*)(sm + xo1 + (uint32_t)((col*4) ^ ((row&7)<<5)));
      float2 ov; ov.x = xv.x + sc*acc[mt][nt][0]; ov.y = xv.y + sc*acc[mt][nt][1];
      *(float2*)(ob + (size_t)row*HWD + col) = ov;
      int row2 = row + 8;
      uint32_t xo2 = (row2 < 40) ? (uint32_t)(STG + row2*512)
                   : (row2 < 80) ? (uint32_t)(2*STG + (row2-40)*512)
                                 : (uint32_t)(3*STG + (row2-80)*512);
      float2 xv2 = *(const float2*)(sm + xo2 + (uint32_t)((col*4) ^ ((row2&7)<<5)));
      float2 ov2; ov2.x = xv2.x + sc*acc[mt][nt][2]; ov2.y = xv2.y + sc*acc[mt][nt][3];
      *(float2*)(ob + (size_t)row2*HWD + col) = ov2;
    }
  }
}

extern "C" void kernel_launch(void* const* d_in, const int* in_sizes, int n_in,
                              void* d_out, int out_size) {
  const float* x     = (const float*)d_in[0];
  const float* w1    = (const float*)d_in[1];
  const float* b1    = (const float*)d_in[2];
  const float* w2    = (const float*)d_in[3];
  const float* b2    = (const float*)d_in[4];
  const float* scale = (const float*)d_in[5];
  float* out = (float*)d_out;

  cudaFuncSetAttribute(k_sinkhorn, cudaFuncAttributeMaxDynamicSharedMemorySize, SMEM_SINK);
  cudaFuncSetAttribute(k_mix, cudaFuncAttributeMaxDynamicSharedMemorySize, SMEM_MIX);

  dim3 gpool(HWD/64, BB);
  k_poolT<<<gpool, 256>>>(x);
  k_fc1<<<BB, RR>>>(w1, b1);
  dim3 gfc2(CC, 4);
  k_fc2_exp<<<gfc2, 256>>>(w2, b2);
  k_sinkhorn<<<BB, 1024, SMEM_SINK>>>();
  dim3 gmix(CC/128, HWD/128, BB);
  k_mix<<<gmix, 256, SMEM_MIX>>>(x, scale, out);
}

// round 15
// speedup vs baseline: 1.3008x; 1.0486x over previous
#include <cuda_runtime.h>
#include <cuda_bf16.h>
#include <cstdint>
#include <cstddef>

#define BB 32
#define CC 256
#define HWD 4096
#define RR 64
#define SINK_IT 6

__device__ float g_pooled[BB*CC];
__device__ float g_h[BB*RR];
__device__ __nv_bfloat16 g_K0[(size_t)BB*CC*CC];
__device__ uint8_t g_M8[(size_t)BB*CC*CC];        // e4m3, M*64
__device__ uint8_t g_x8[(size_t)BB*HWD*CC];       // e4m3 x^T

__device__ __forceinline__ uint32_t s2u(const void* p) {
  return (uint32_t)__cvta_generic_to_shared(p);
}
__device__ __forceinline__ void cp16(uint32_t d, const void* s) {
  asm volatile("cp.async.cg.shared.global [%0], [%1], 16;" :: "r"(d), "l"(s));
}
__device__ __forceinline__ uint32_t fp8x2(float lo, float hi) {
  uint16_t r;
  asm("cvt.rn.satfinite.e4m3x2.f32 %0, %1, %2;" : "=h"(r) : "f"(hi), "f"(lo));
  return (uint32_t)r;
}

// ===== K1: transpose x -> e4m3 x8, pooled partials (double-buffer, 4 syncs) =
__global__ void __launch_bounds__(256) k_poolT(const float* __restrict__ x) {
  __shared__ float ts[2][64*68];
  const int b = blockIdx.y, n0 = blockIdx.x * 64, t = threadIdx.x;
  const int rl = t >> 2, c4 = t & 3;
  const int nw = t & 63, cw = (t >> 6) * 16;
  float4 a, bq, cq, dq;
  {
    const float4* src = (const float4*)(x + ((size_t)b*CC + rl)*HWD + n0 + c4*16);
    a = src[0]; bq = src[1]; cq = src[2]; dq = src[3];
  }
  for (int cg = 0; cg < 4; cg++) {
    float* buf = ts[cg & 1];
    float4* tr = (float4*)(buf + rl*68 + c4*16);
    tr[0]=a; tr[1]=bq; tr[2]=cq; tr[3]=dq;
    float s = (a.x+a.y+a.z+a.w) + (bq.x+bq.y+bq.z+bq.w)
            + (cq.x+cq.y+cq.z+cq.w) + (dq.x+dq.y+dq.z+dq.w);
    s += __shfl_xor_sync(0xffffffffu, s, 1);
    s += __shfl_xor_sync(0xffffffffu, s, 2);
    if (c4 == 0) atomicAdd(&g_pooled[b*CC + cg*64 + rl], s);
    if (cg < 3) {   // prefetch next group's rows (overlaps sync + reads)
      const float4* src = (const float4*)(x + ((size_t)b*CC + (cg+1)*64 + rl)*HWD + n0 + c4*16);
      a = src[0]; bq = src[1]; cq = src[2]; dq = src[3];
    }
    __syncthreads();
    uint32_t pk[4];
    #pragma unroll
    for (int i = 0; i < 4; i++) {
      float v0 = buf[(cw + 4*i + 0)*68 + nw];
      float v1 = buf[(cw + 4*i + 1)*68 + nw];
      float v2 = buf[(cw + 4*i + 2)*68 + nw];
      float v3 = buf[(cw + 4*i + 3)*68 + nw];
      pk[i] = fp8x2(v0, v1) | (fp8x2(v2, v3) << 16);
    }
    uint8_t* dst = g_x8 + ((size_t)b*HWD + n0 + nw)*CC + cg*64 + cw;
    *(uint4*)dst = make_uint4(pk[0], pk[1], pk[2], pk[3]);
  }
}

// ============ K2: h = silu(mean @ w1^T + b1); zero pooled for next replay ===
__global__ void k_fc1(const float* __restrict__ w1, const float* __restrict__ b1) {
  int b = blockIdx.x, r = threadIdx.x;
  __shared__ float p[CC];
  for (int k = r; k < CC; k += RR) p[k] = g_pooled[b*CC + k] * (1.0f/4096.0f);
  __syncthreads();
  for (int k = r; k < CC; k += RR) g_pooled[b*CC + k] = 0.f;
  const float4* wr = (const float4*)(w1 + (size_t)r * CC);
  float acc = b1[r];
  #pragma unroll 8
  for (int k = 0; k < 64; k++) {
    float4 w = wr[k];
    acc += w.x*p[4*k] + w.y*p[4*k+1] + w.z*p[4*k+2] + w.w*p[4*k+3];
  }
  g_h[b*RR + r] = acc / (1.0f + __expf(-acc));
}

// ============ K3: weights -> exp(w - rowmax) -> K0; 16 batches/block ========
__global__ void __launch_bounds__(256) k_fc2_exp(const float* __restrict__ w2,
                                                 const float* __restrict__ b2) {
  const int i = blockIdx.x, j = threadIdx.x;
  const int b0 = blockIdx.y * 16;
  const int w = j >> 5, l = j & 31;
  __shared__ float hs[16*RR];
  __shared__ float red[8*16];
  for (int tt = j; tt < 16*RR; tt += 256) hs[tt] = g_h[b0*RR + tt];
  __syncthreads();

  const float4* w2r = (const float4*)(w2 + (size_t)(i*CC + j) * RR);
  const float bv = b2[i*CC + j];
  float acc[16];
  #pragma unroll
  for (int b = 0; b < 16; b++) acc[b] = bv;
  #pragma unroll
  for (int k4 = 0; k4 < 16; k4++) {
    float4 wv = w2r[k4];
    #pragma unroll
    for (int b = 0; b < 16; b++) {
      const float* hb = hs + b*64 + k4*4;
      acc[b] += wv.x*hb[0] + wv.y*hb[1] + wv.z*hb[2] + wv.w*hb[3];
    }
  }
  #pragma unroll
  for (int b = 0; b < 16; b++) {
    float m = acc[b];
    #pragma unroll
    for (int o = 16; o; o >>= 1) m = fmaxf(m, __shfl_xor_sync(0xffffffffu, m, o));
    if (l == b) red[w*16 + b] = m;
  }
  __syncthreads();
  #pragma unroll
  for (int b = 0; b < 16; b++) {
    float bm = red[b];
    #pragma unroll
    for (int ww = 1; ww < 8; ww++) bm = fmaxf(bm, red[ww*16 + b]);
    float e = __expf(acc[b] - bm);
    float eo = __shfl_down_sync(0xffffffffu, e, 1);
    if ((j & 1) == 0) {
      __nv_bfloat162 pk;
      pk.x = __float2bfloat16(e); pk.y = __float2bfloat16(eo);
      *(__nv_bfloat162*)(g_K0 + ((size_t)((b0 + b)*CC + i))*CC + j) = pk;
    }
  }
}

// ============ K4: Sinkhorn u/v scaling form, HFMA2, 6 iters ============
#define KP 264
#define SMEM_SINK (256*KP*2 + 8*256*4 + 256*4 + 256*4 + 256*4 + 128*4)
__global__ void __launch_bounds__(1024, 1) k_sinkhorn() {
  extern __shared__ char smC[];
  __nv_bfloat16* Kb = (__nv_bfloat16*)smC;
  float* red = (float*)(smC + 256*KP*2);
  float* u = red + 8*256;
  float* v = u + 256;
  uint32_t* ub2 = (uint32_t*)(v + 256);
  uint32_t* vb2 = ub2 + 256;
  const int b = blockIdx.x, t = threadIdx.x;
  const __nv_bfloat16* src = g_K0 + (size_t)b * (CC*CC);
  #pragma unroll
  for (int i = 0; i < 8; i++) {
    int idx = t + 1024*i;
    int r = idx >> 5, c8 = idx & 31;
    float4 d = *(const float4*)(src + r*CC + c8*8);
    *(float4*)(Kb + r*KP + c8*8) = d;
  }
  if (t < 256) v[t] = 1.0f;
  if (t < 128) vb2[t] = 0x3F803F80u;
  __syncthreads();

  const int rr = t & 255, q = t >> 8;
  const int cp_ = t & 127, rg = t >> 7;
  const __nv_bfloat162 z2 = __floats2bfloat162_rn(0.f, 0.f);

  for (int it = 0; it < SINK_IT; it++) {
    {
      __nv_bfloat162 a8[8];
      #pragma unroll
      for (int a = 0; a < 8; a++) a8[a] = z2;
      const uint4* kp4 = (const uint4*)(Kb + rr*KP + q*64);
      const uint4* vp4 = (const uint4*)(vb2 + q*32);
      #pragma unroll
      for (int i = 0; i < 8; i++) {
        uint4 kk = kp4[i]; uint4 vv = vp4[i];
        const uint32_t* kw = &kk.x; const uint32_t* vw = &vv.x;
        #pragma unroll
        for (int j = 0; j < 4; j++) {
          a8[(i&1)*4+j] = __hfma2(*(const __nv_bfloat162*)&kw[j],
                                  *(const __nv_bfloat162*)&vw[j], a8[(i&1)*4+j]);
        }
      }
      float s = 0.f;
      #pragma unroll
      for (int a = 0; a < 8; a++) {
        float2 f = __bfloat1622float2(a8[a]);
        s += f.x + f.y;
      }
      red[q*256 + rr] = s;
    }
    __syncthreads();
    if (t < 256) {
      float s = red[t] + red[256+t] + red[512+t] + red[768+t];
      float uu = 1.0f / (s + 1e-12f);
      u[t] = uu;
      __nv_bfloat16 ub = __float2bfloat16(uu);
      __nv_bfloat162 up; up.x = ub; up.y = ub;
      ub2[t] = *(uint32_t*)&up;
    }
    __syncthreads();
    {
      __nv_bfloat162 a8[8];
      #pragma unroll
      for (int a = 0; a < 8; a++) a8[a] = z2;
      const __nv_bfloat16* base = Kb + (rg*32)*KP + 2*cp_;
      const uint32_t* up = ub2 + rg*32;
      #pragma unroll
      for (int i = 0; i < 32; i++) {
        uint32_t k2 = *(const uint32_t*)(base + i*KP);
        uint32_t uu = up[i];
        a8[i&7] = __hfma2(*(const __nv_bfloat162*)&k2,
                          *(const __nv_bfloat162*)&uu, a8[i&7]);
      }
      float a0 = 0.f, a1 = 0.f;
      #pragma unroll
      for (int a = 0; a < 8; a++) {
        float2 f = __bfloat1622float2(a8[a]);
        a0 += f.x; a1 += f.y;
      }
      float2 w2v; w2v.x = a0; w2v.y = a1;
      *(float2*)(red + rg*256 + 2*cp_) = w2v;
    }
    __syncthreads();
    if (t < 256) {
      float s = 0.f;
      #pragma unroll
      for (int g = 0; g < 8; g++) s += red[g*256 + t];
      float vv = 1.0f / (s + 1e-12f);
      v[t] = vv;
      float vn = __shfl_xor_sync(0xffffffffu, vv, 1);
      if ((t & 1) == 0) {
        __nv_bfloat162 vp; vp.x = __float2bfloat16(vv); vp.y = __float2bfloat16(vn);
        vb2[t >> 1] = *(uint32_t*)&vp;
      }
    }
    __syncthreads();
  }
  for (int idx = t; idx < 16384; idx += 1024) {
    int i = idx >> 6, c4 = idx & 63;
    float su = 64.0f * u[i];
    const __nv_bfloat16* rp = Kb + i*KP + 4*c4;
    float m0 = su * __bfloat162float(rp[0]) * v[4*c4+0];
    float m1 = su * __bfloat162float(rp[1]) * v[4*c4+1];
    float m2 = su * __bfloat162float(rp[2]) * v[4*c4+2];
    float m3 = su * __bfloat162float(rp[3]) * v[4*c4+3];
    uint32_t pk = fp8x2(m0, m1) | (fp8x2(m2, m3) << 16);
    *(uint32_t*)(g_M8 + (size_t)b*(CC*CC) + i*CC + 4*c4) = pk;
  }
}

// ===== K5: out = x + (scale/64)*M8@x8^T — 3-stage pipe + smem x residual ====
#define APITCH 80
#define ASTG (128*APITCH)
#define STG (2*ASTG)
#define XPAD (48*512)
#define SMEM_MIX (3*STG + XPAD)
__global__ void __launch_bounds__(256, 2) k_mix(const float* __restrict__ x,
                                                const float* __restrict__ scale,
                                                float* __restrict__ out) {
  extern __shared__ __align__(128) char sm[];
  const int t = threadIdx.x;
  const int m0 = blockIdx.x * 128;
  const int n0 = blockIdx.y * 128;
  const int b  = blockIdx.z;
  const uint32_t s0 = s2u(sm);
  const int w = t >> 5, l = t & 31;
  const int wm = (w & 1) * 64, wn = (w >> 1) * 32;
  const int g = l >> 3, r = l & 7;
  const int lrow = r + (g & 1) * 8;
  const int lchunk = (g >> 1) * 16;

  const uint8_t* Ab = g_M8 + ((size_t)b << 16) + (size_t)m0 * CC;
  const uint8_t* Bb = g_x8 + ((size_t)b << 20) + (size_t)n0 * CC;
  const float* xsrc = x + ((size_t)b*CC + m0)*HWD + n0;

  #define PREFETCH(kc) {                                                        \
    uint32_t As_ = s0 + ((kc) % 3) * STG;                                       \
    uint32_t Bs_ = As_ + ASTG;                                                  \
    _Pragma("unroll")                                                           \
    for (int i_ = 0; i_ < 2; i_++) {                                            \
      int idx = t + 256*i_; int rw = idx >> 2, c_ = idx & 3;                    \
      cp16(As_ + rw*APITCH + c_*16, Ab + (size_t)rw*CC + (kc)*64 + c_*16);      \
      cp16(Bs_ + rw*APITCH + c_*16, Bb + (size_t)rw*CC + (kc)*64 + c_*16);      \
    }                                                                           \
    asm volatile("cp.async.commit_group;");                                     \
  }
  #define XLD(base, r0, cnt) {                                                  \
    _Pragma("unroll")                                                           \
    for (int i_ = 0; i_ < (cnt); i_++) {                                        \
      int idx = t + 256*i_; int rr_ = (idx >> 5), c16 = idx & 31;               \
      int rg_ = (r0) + rr_;                                                     \
      cp16(s0 + (base) + (uint32_t)rr_*512 + (uint32_t)((c16*16) ^ ((rg_&7)<<5)),\
           xsrc + (size_t)rg_*HWD + c16*4);                                     \
    }                                                                           \
    asm volatile("cp.async.commit_group;");                                     \
  }
  #define COMPUTE(kc) {                                                         \
    uint32_t Ast = s0 + ((kc) % 3) * STG;                                       \
    uint32_t Bst = Ast + ASTG;                                                  \
    uint32_t abase = Ast + (uint32_t)(wm + lrow)*APITCH + lchunk;               \
    uint32_t bbase = Bst + (uint32_t)(wn + lrow)*APITCH + lchunk;               \
    _Pragma("unroll")                                                           \
    for (int ks = 0; ks < 2; ks++) {                                            \
      uint32_t bfr[4][2];                                                       \
      _Pragma("unroll")                                                         \
      for (int ng = 0; ng < 2; ng++) {                                          \
        uint32_t r0, r1, r2, r3;                                                \
        asm volatile("ldmatrix.sync.aligned.m8n8.x4.shared.b16 {%0,%1,%2,%3}, [%4];" \
                     : "=r"(r0), "=r"(r1), "=r"(r2), "=r"(r3)                   \
                     : "r"(bbase + ng*16*APITCH + ks*32));                      \
        bfr[2*ng][0]=r0; bfr[2*ng+1][0]=r1; bfr[2*ng][1]=r2; bfr[2*ng+1][1]=r3; \
      }                                                                         \
      _Pragma("unroll")                                                         \
      for (int mt = 0; mt < 4; mt++) {                                          \
        uint32_t a0, a1, a2, a3;                                                \
        asm volatile("ldmatrix.sync.aligned.m8n8.x4.shared.b16 {%0,%1,%2,%3}, [%4];" \
                     : "=r"(a0), "=r"(a1), "=r"(a2), "=r"(a3)                   \
                     : "r"(abase + mt*16*APITCH + ks*32));                      \
        _Pragma("unroll")                                                       \
        for (int nt = 0; nt < 4; nt++) {                                        \
          asm volatile("mma.sync.aligned.m16n8k32.row.col.f32.e4m3.e4m3.f32 "   \
                       "{%0,%1,%2,%3}, {%4,%5,%6,%7}, {%8,%9}, {%0,%1,%2,%3};"  \
                       : "+f"(acc[mt][nt][0]), "+f"(acc[mt][nt][1]),            \
                         "+f"(acc[mt][nt][2]), "+f"(acc[mt][nt][3])             \
                       : "r"(a0), "r"(a1), "r"(a2), "r"(a3),                    \
                         "r"(bfr[nt][0]), "r"(bfr[nt][1]));                     \
        }                                                                       \
      }                                                                         \
    }                                                                           \
  }

  float acc[4][4][4];
  #pragma unroll
  for (int mt = 0; mt < 4; mt++)
    #pragma unroll
    for (int nt = 0; nt < 4; nt++)
      #pragma unroll
      for (int qq = 0; qq < 4; qq++) acc[mt][nt][qq] = 0.f;

  PREFETCH(0)                 // c1
  PREFETCH(1)                 // c2
  XLD(3*STG, 80, 6)           // c3: x rows 80..127 -> pad (always free)

  asm volatile("cp.async.wait_group 2;" ::: "memory");  // c1 done
  __syncthreads();
  PREFETCH(2)                 // c4
  COMPUTE(0)

  asm volatile("cp.async.wait_group 2;" ::: "memory");  // c2 done
  __syncthreads();
  PREFETCH(3)                 // c5
  COMPUTE(1)

  asm volatile("cp.async.wait_group 1;" ::: "memory");  // c4 done
  __syncthreads();
  XLD(STG, 0, 5)              // c6: x rows 0..39 -> stage1 (now free)
  COMPUTE(2)

  asm volatile("cp.async.wait_group 1;" ::: "memory");  // c5 done
  __syncthreads();
  XLD(2*STG, 40, 5)           // c7: x rows 40..79 -> stage2 (now free)
  COMPUTE(3)

  asm volatile("cp.async.wait_group 0;" ::: "memory");  // all x arrived
  __syncthreads();

  const float sc = scale[0] * 0.015625f;
  float* ob = out + ((size_t)b*CC + m0)*HWD + n0;
  const int er = l >> 2, ec = 2 * (l & 3);
  #pragma unroll
  for (int mt = 0; mt < 4; mt++) {
    #pragma unroll
    for (int nt = 0; nt < 4; nt++) {
      int row = wm + mt*16 + er;
      int col = wn + nt*8 + ec;
      uint32_t xo1 = (row < 40) ? (uint32_t)(STG + row*512)
                   : (row < 80) ? (uint32_t)(2*STG + (row-40)*512)
                                : (uint32_t)(3*STG + (row-80)*512);
      float2 xv = *(const float2*)(sm + xo1 + (uint32_t)((col*4) ^ ((row&7)<<5)));
      float2 ov; ov.x = xv.x + sc*acc[mt][nt][0]; ov.y = xv.y + sc*acc[mt][nt][1];
      *(float2*)(ob + (size_t)row*HWD + col) = ov;
      int row2 = row + 8;
      uint32_t xo2 = (row2 < 40) ? (uint32_t)(STG + row2*512)
                   : (row2 < 80) ? (uint32_t)(2*STG + (row2-40)*512)
                                 : (uint32_t)(3*STG + (row2-80)*512);
      float2 xv2 = *(const float2*)(sm + xo2 + (uint32_t)((col*4) ^ ((row2&7)<<5)));
      float2 ov2; ov2.x = xv2.x + sc*acc[mt][nt][2]; ov2.y = xv2.y + sc*acc[mt][nt][3];
      *(float2*)(ob + (size_t)row2*HWD + col) = ov2;
    }
  }
}

extern "C" void kernel_launch(void* const* d_in, const int* in_sizes, int n_in,
                              void* d_out, int out_size) {
  const float* x     = (const float*)d_in[0];
  const float* w1    = (const float*)d_in[1];
  const float* b1    = (const float*)d_in[2];
  const float* w2    = (const float*)d_in[3];
  const float* b2    = (const float*)d_in[4];
  const float* scale = (const float*)d_in[5];
  float* out = (float*)d_out;

  cudaFuncSetAttribute(k_sinkhorn, cudaFuncAttributeMaxDynamicSharedMemorySize, SMEM_SINK);
  cudaFuncSetAttribute(k_mix, cudaFuncAttributeMaxDynamicSharedMemorySize, SMEM_MIX);

  dim3 gpool(HWD/64, BB);
  k_poolT<<<gpool, 256>>>(x);
  k_fc1<<<BB, RR>>>(w1, b1);
  dim3 gfc2(CC, 2);
  k_fc2_exp<<<gfc2, 256>>>(w2, b2);
  k_sinkhorn<<<BB, 1024, SMEM_SINK>>>();
  dim3 gmix(CC/128, HWD/128, BB);
  k_mix<<<gmix, 256, SMEM_MIX>>>(x, scale, out);
}

// round 16
// speedup vs baseline: 1.3492x; 1.0372x over previous
#include <cuda_runtime.h>
#include <cuda_bf16.h>
#include <cstdint>
#include <cstddef>

#define BB 32
#define CC 256
#define HWD 4096
#define RR 64
#define SINK_IT 5

__device__ float g_pooled[BB*CC];
__device__ float g_h[BB*RR];
__device__ __nv_bfloat16 g_K0[(size_t)BB*CC*CC];
__device__ uint8_t g_M8[(size_t)BB*CC*CC];        // e4m3, M*64
__device__ uint8_t g_x8[(size_t)BB*HWD*CC];       // e4m3 x^T

__device__ __forceinline__ uint32_t s2u(const void* p) {
  return (uint32_t)__cvta_generic_to_shared(p);
}
__device__ __forceinline__ void cp16(uint32_t d, const void* s) {
  asm volatile("cp.async.cg.shared.global [%0], [%1], 16;" :: "r"(d), "l"(s));
}
__device__ __forceinline__ uint32_t fp8x2(float lo, float hi) {
  uint16_t r;
  asm("cvt.rn.satfinite.e4m3x2.f32 %0, %1, %2;" : "=h"(r) : "f"(hi), "f"(lo));
  return (uint32_t)r;
}

// ============ K1: transpose x -> e4m3 x8, partial pooled sums (R11) ========
__global__ void __launch_bounds__(256) k_poolT(const float* __restrict__ x) {
  __shared__ float ts[64*68];
  const int b = blockIdx.y, n0 = blockIdx.x * 64, t = threadIdx.x;
  const int rl = t >> 2, c4 = t & 3;
  const int nw = t & 63, cw = (t >> 6) * 16;
  for (int cg = 0; cg < 4; cg++) {
    int ch = cg*64 + rl;
    const float4* src = (const float4*)(x + ((size_t)b*CC + ch)*HWD + n0 + c4*16);
    float4 a = src[0], bq = src[1], cq = src[2], dq = src[3];
    float4* tr = (float4*)(ts + rl*68 + c4*16);
    tr[0]=a; tr[1]=bq; tr[2]=cq; tr[3]=dq;
    float s = (a.x+a.y+a.z+a.w) + (bq.x+bq.y+bq.z+bq.w)
            + (cq.x+cq.y+cq.z+cq.w) + (dq.x+dq.y+dq.z+dq.w);
    s += __shfl_xor_sync(0xffffffffu, s, 1);
    s += __shfl_xor_sync(0xffffffffu, s, 2);
    if (c4 == 0) atomicAdd(&g_pooled[b*CC + ch], s);
    __syncthreads();
    uint32_t pk[4];
    #pragma unroll
    for (int i = 0; i < 4; i++) {
      float v0 = ts[(cw + 4*i + 0)*68 + nw];
      float v1 = ts[(cw + 4*i + 1)*68 + nw];
      float v2 = ts[(cw + 4*i + 2)*68 + nw];
      float v3 = ts[(cw + 4*i + 3)*68 + nw];
      pk[i] = fp8x2(v0, v1) | (fp8x2(v2, v3) << 16);
    }
    uint8_t* dst = g_x8 + ((size_t)b*HWD + n0 + nw)*CC + cg*64 + cw;
    *(uint4*)dst = make_uint4(pk[0], pk[1], pk[2], pk[3]);
    __syncthreads();
  }
}

// ============ K2: h = silu(mean @ w1^T + b1); zero pooled for next replay ===
__global__ void k_fc1(const float* __restrict__ w1, const float* __restrict__ b1) {
  int b = blockIdx.x, r = threadIdx.x;
  __shared__ float p[CC];
  for (int k = r; k < CC; k += RR) p[k] = g_pooled[b*CC + k] * (1.0f/4096.0f);
  __syncthreads();
  for (int k = r; k < CC; k += RR) g_pooled[b*CC + k] = 0.f;
  const float4* wr = (const float4*)(w1 + (size_t)r * CC);
  float acc = b1[r];
  #pragma unroll 8
  for (int k = 0; k < 64; k++) {
    float4 w = wr[k];
    acc += w.x*p[4*k] + w.y*p[4*k+1] + w.z*p[4*k+2] + w.w*p[4*k+3];
  }
  g_h[b*RR + r] = acc / (1.0f + __expf(-acc));
}

// ============ K3: weights -> exp(w - rowmax) -> K0; 16 batches/block ========
__global__ void __launch_bounds__(256) k_fc2_exp(const float* __restrict__ w2,
                                                 const float* __restrict__ b2) {
  const int i = blockIdx.x, j = threadIdx.x;
  const int b0 = blockIdx.y * 16;
  const int w = j >> 5, l = j & 31;
  __shared__ float hs[16*RR];
  __shared__ float red[8*16];
  for (int tt = j; tt < 16*RR; tt += 256) hs[tt] = g_h[b0*RR + tt];
  __syncthreads();

  const float4* w2r = (const float4*)(w2 + (size_t)(i*CC + j) * RR);
  const float bv = b2[i*CC + j];
  float acc[16];
  #pragma unroll
  for (int b = 0; b < 16; b++) acc[b] = bv;
  #pragma unroll
  for (int k4 = 0; k4 < 16; k4++) {
    float4 wv = w2r[k4];
    #pragma unroll
    for (int b = 0; b < 16; b++) {
      float4 hv = *(const float4*)(hs + b*64 + k4*4);   // LDS.128 broadcast
      acc[b] += wv.x*hv.x + wv.y*hv.y + wv.z*hv.z + wv.w*hv.w;
    }
  }
  #pragma unroll
  for (int b = 0; b < 16; b++) {
    float m = acc[b];
    #pragma unroll
    for (int o = 16; o; o >>= 1) m = fmaxf(m, __shfl_xor_sync(0xffffffffu, m, o));
    if (l == b) red[w*16 + b] = m;
  }
  __syncthreads();
  #pragma unroll
  for (int b = 0; b < 16; b++) {
    float bm = red[b];
    #pragma unroll
    for (int ww = 1; ww < 8; ww++) bm = fmaxf(bm, red[ww*16 + b]);
    float e = __expf(acc[b] - bm);
    float eo = __shfl_down_sync(0xffffffffu, e, 1);
    if ((j & 1) == 0) {
      __nv_bfloat162 pk;
      pk.x = __float2bfloat16(e); pk.y = __float2bfloat16(eo);
      *(__nv_bfloat162*)(g_K0 + ((size_t)((b0 + b)*CC + i))*CC + j) = pk;
    }
  }
}

// ============ K4: Sinkhorn u/v scaling form, HFMA2, 5 iters ============
#define KP 264
#define SMEM_SINK (256*KP*2 + 8*256*4 + 256*4 + 256*4 + 256*4 + 128*4)
__global__ void __launch_bounds__(1024, 1) k_sinkhorn() {
  extern __shared__ char smC[];
  __nv_bfloat16* Kb = (__nv_bfloat16*)smC;
  float* red = (float*)(smC + 256*KP*2);
  float* u = red + 8*256;
  float* v = u + 256;
  uint32_t* ub2 = (uint32_t*)(v + 256);
  uint32_t* vb2 = ub2 + 256;
  const int b = blockIdx.x, t = threadIdx.x;
  const __nv_bfloat16* src = g_K0 + (size_t)b * (CC*CC);
  #pragma unroll
  for (int i = 0; i < 8; i++) {
    int idx = t + 1024*i;
    int r = idx >> 5, c8 = idx & 31;
    float4 d = *(const float4*)(src + r*CC + c8*8);
    *(float4*)(Kb + r*KP + c8*8) = d;
  }
  if (t < 256) v[t] = 1.0f;
  if (t < 128) vb2[t] = 0x3F803F80u;
  __syncthreads();

  const int rr = t & 255, q = t >> 8;
  const int cp_ = t & 127, rg = t >> 7;
  const __nv_bfloat162 z2 = __floats2bfloat162_rn(0.f, 0.f);

  for (int it = 0; it < SINK_IT; it++) {
    {
      __nv_bfloat162 a8[8];
      #pragma unroll
      for (int a = 0; a < 8; a++) a8[a] = z2;
      const uint4* kp4 = (const uint4*)(Kb + rr*KP + q*64);
      const uint4* vp4 = (const uint4*)(vb2 + q*32);
      #pragma unroll
      for (int i = 0; i < 8; i++) {
        uint4 kk = kp4[i]; uint4 vv = vp4[i];
        const uint32_t* kw = &kk.x; const uint32_t* vw = &vv.x;
        #pragma unroll
        for (int j = 0; j < 4; j++) {
          a8[(i&1)*4+j] = __hfma2(*(const __nv_bfloat162*)&kw[j],
                                  *(const __nv_bfloat162*)&vw[j], a8[(i&1)*4+j]);
        }
      }
      float s = 0.f;
      #pragma unroll
      for (int a = 0; a < 8; a++) {
        float2 f = __bfloat1622float2(a8[a]);
        s += f.x + f.y;
      }
      red[q*256 + rr] = s;
    }
    __syncthreads();
    if (t < 256) {
      float s = red[t] + red[256+t] + red[512+t] + red[768+t];
      float uu = 1.0f / (s + 1e-12f);
      u[t] = uu;
      __nv_bfloat16 ub = __float2bfloat16(uu);
      __nv_bfloat162 up; up.x = ub; up.y = ub;
      ub2[t] = *(uint32_t*)&up;
    }
    __syncthreads();
    {
      __nv_bfloat162 a8[8];
      #pragma unroll
      for (int a = 0; a < 8; a++) a8[a] = z2;
      const __nv_bfloat16* base = Kb + (rg*32)*KP + 2*cp_;
      const uint32_t* up = ub2 + rg*32;
      #pragma unroll
      for (int i = 0; i < 32; i++) {
        uint32_t k2 = *(const uint32_t*)(base + i*KP);
        uint32_t uu = up[i];
        a8[i&7] = __hfma2(*(const __nv_bfloat162*)&k2,
                          *(const __nv_bfloat162*)&uu, a8[i&7]);
      }
      float a0 = 0.f, a1 = 0.f;
      #pragma unroll
      for (int a = 0; a < 8; a++) {
        float2 f = __bfloat1622float2(a8[a]);
        a0 += f.x; a1 += f.y;
      }
      float2 w2v; w2v.x = a0; w2v.y = a1;
      *(float2*)(red + rg*256 + 2*cp_) = w2v;
    }
    __syncthreads();
    if (t < 256) {
      float s = 0.f;
      #pragma unroll
      for (int g = 0; g < 8; g++) s += red[g*256 + t];
      float vv = 1.0f / (s + 1e-12f);
      v[t] = vv;
      float vn = __shfl_xor_sync(0xffffffffu, vv, 1);
      if ((t & 1) == 0) {
        __nv_bfloat162 vp; vp.x = __float2bfloat16(vv); vp.y = __float2bfloat16(vn);
        vb2[t >> 1] = *(uint32_t*)&vp;
      }
    }
    __syncthreads();
  }
  for (int idx = t; idx < 16384; idx += 1024) {
    int i = idx >> 6, c4 = idx & 63;
    float su = 64.0f * u[i];
    const __nv_bfloat16* rp = Kb + i*KP + 4*c4;
    float m0 = su * __bfloat162float(rp[0]) * v[4*c4+0];
    float m1 = su * __bfloat162float(rp[1]) * v[4*c4+1];
    float m2 = su * __bfloat162float(rp[2]) * v[4*c4+2];
    float m3 = su * __bfloat162float(rp[3]) * v[4*c4+3];
    uint32_t pk = fp8x2(m0, m1) | (fp8x2(m2, m3) << 16);
    *(uint32_t*)(g_M8 + (size_t)b*(CC*CC) + i*CC + 4*c4) = pk;
  }
}

// ===== K5: out = x + (scale/64)*M8@x8^T — 3-stage pipe + smem x residual ====
#define APITCH 80
#define ASTG (128*APITCH)
#define STG (2*ASTG)
#define XPAD (48*512)
#define SMEM_MIX (3*STG + XPAD)
__global__ void __launch_bounds__(256, 2) k_mix(const float* __restrict__ x,
                                                const float* __restrict__ scale,
                                                float* __restrict__ out) {
  extern __shared__ __align__(128) char sm[];
  const int t = threadIdx.x;
  const int m0 = blockIdx.x * 128;
  const int n0 = blockIdx.y * 128;
  const int b  = blockIdx.z;
  const uint32_t s0 = s2u(sm);
  const int w = t >> 5, l = t & 31;
  const int wm = (w & 1) * 64, wn = (w >> 1) * 32;
  const int g = l >> 3, r = l & 7;
  const int lrow = r + (g & 1) * 8;
  const int lchunk = (g >> 1) * 16;

  const uint8_t* Ab = g_M8 + ((size_t)b << 16) + (size_t)m0 * CC;
  const uint8_t* Bb = g_x8 + ((size_t)b << 20) + (size_t)n0 * CC;
  const float* xsrc = x + ((size_t)b*CC + m0)*HWD + n0;

  #define PREFETCH(kc) {                                                        \
    uint32_t As_ = s0 + ((kc) % 3) * STG;                                       \
    uint32_t Bs_ = As_ + ASTG;                                                  \
    _Pragma("unroll")                                                           \
    for (int i_ = 0; i_ < 2; i_++) {                                            \
      int idx = t + 256*i_; int rw = idx >> 2, c_ = idx & 3;                    \
      cp16(As_ + rw*APITCH + c_*16, Ab + (size_t)rw*CC + (kc)*64 + c_*16);      \
      cp16(Bs_ + rw*APITCH + c_*16, Bb + (size_t)rw*CC + (kc)*64 + c_*16);      \
    }                                                                           \
    asm volatile("cp.async.commit_group;");                                     \
  }
  #define XLD(base, r0, cnt) {                                                  \
    _Pragma("unroll")                                                           \
    for (int i_ = 0; i_ < (cnt); i_++) {                                        \
      int idx = t + 256*i_; int rr_ = (idx >> 5), c16 = idx & 31;               \
      int rg_ = (r0) + rr_;                                                     \
      cp16(s0 + (base) + (uint32_t)rr_*512 + (uint32_t)((c16*16) ^ ((rg_&7)<<5)),\
           xsrc + (size_t)rg_*HWD + c16*4);                                     \
    }                                                                           \
    asm volatile("cp.async.commit_group;");                                     \
  }
  #define COMPUTE(kc) {                                                         \
    uint32_t Ast = s0 + ((kc) % 3) * STG;                                       \
    uint32_t Bst = Ast + ASTG;                                                  \
    uint32_t abase = Ast + (uint32_t)(wm + lrow)*APITCH + lchunk;               \
    uint32_t bbase = Bst + (uint32_t)(wn + lrow)*APITCH + lchunk;               \
    _Pragma("unroll")                                                           \
    for (int ks = 0; ks < 2; ks++) {                                            \
      uint32_t bfr[4][2];                                                       \
      _Pragma("unroll")                                                         \
      for (int ng = 0; ng < 2; ng++) {                                          \
        uint32_t r0, r1, r2, r3;                                                \
        asm volatile("ldmatrix.sync.aligned.m8n8.x4.shared.b16 {%0,%1,%2,%3}, [%4];" \
                     : "=r"(r0), "=r"(r1), "=r"(r2), "=r"(r3)                   \
                     : "r"(bbase + ng*16*APITCH + ks*32));                      \
        bfr[2*ng][0]=r0; bfr[2*ng+1][0]=r1; bfr[2*ng][1]=r2; bfr[2*ng+1][1]=r3; \
      }                                                                         \
      _Pragma("unroll")                                                         \
      for (int mt = 0; mt < 4; mt++) {                                          \
        uint32_t a0, a1, a2, a3;                                                \
        asm volatile("ldmatrix.sync.aligned.m8n8.x4.shared.b16 {%0,%1,%2,%3}, [%4];" \
                     : "=r"(a0), "=r"(a1), "=r"(a2), "=r"(a3)                   \
                     : "r"(abase + mt*16*APITCH + ks*32));                      \
        _Pragma("unroll")                                                       \
        for (int nt = 0; nt < 4; nt++) {                                        \
          asm volatile("mma.sync.aligned.m16n8k32.row.col.f32.e4m3.e4m3.f32 "   \
                       "{%0,%1,%2,%3}, {%4,%5,%6,%7}, {%8,%9}, {%0,%1,%2,%3};"  \
                       : "+f"(acc[mt][nt][0]), "+f"(acc[mt][nt][1]),            \
                         "+f"(acc[mt][nt][2]), "+f"(acc[mt][nt][3])             \
                       : "r"(a0), "r"(a1), "r"(a2), "r"(a3),                    \
                         "r"(bfr[nt][0]), "r"(bfr[nt][1]));                     \
        }                                                                       \
      }                                                                         \
    }                                                                           \
  }

  float acc[4][4][4];
  #pragma unroll
  for (int mt = 0; mt < 4; mt++)
    #pragma unroll
    for (int nt = 0; nt < 4; nt++)
      #pragma unroll
      for (int qq = 0; qq < 4; qq++) acc[mt][nt][qq] = 0.f;

  PREFETCH(0)                 // c1
  PREFETCH(1)                 // c2
  XLD(3*STG, 80, 6)           // c3: x rows 80..127 -> pad (always free)

  asm volatile("cp.async.wait_group 2;" ::: "memory");  // c1 done
  __syncthreads();
  PREFETCH(2)                 // c4
  COMPUTE(0)

  asm volatile("cp.async.wait_group 2;" ::: "memory");  // c2 done
  __syncthreads();
  PREFETCH(3)                 // c5
  COMPUTE(1)

  asm volatile("cp.async.wait_group 1;" ::: "memory");  // c4 done
  __syncthreads();
  XLD(STG, 0, 5)              // c6: x rows 0..39 -> stage1 (now free)
  COMPUTE(2)

  asm volatile("cp.async.wait_group 1;" ::: "memory");  // c5 done
  __syncthreads();
  XLD(2*STG, 40, 5)           // c7: x rows 40..79 -> stage2 (now free)
  COMPUTE(3)

  asm volatile("cp.async.wait_group 0;" ::: "memory");  // all x arrived
  __syncthreads();

  const float sc = scale[0] * 0.015625f;
  float* ob = out + ((size_t)b*CC + m0)*HWD + n0;
  const int er = l >> 2, ec = 2 * (l & 3);
  #pragma unroll
  for (int mt = 0; mt < 4; mt++) {
    #pragma unroll
    for (int nt = 0; nt < 4; nt++) {
      int row = wm + mt*16 + er;
      int col = wn + nt*8 + ec;
      uint32_t xo1 = (row < 40) ? (uint32_t)(STG + row*512)
                   : (row < 80) ? (uint32_t)(2*STG + (row-40)*512)
                                : (uint32_t)(3*STG + (row-80)*512);
      float2 xv = *(const float2*)(sm + xo1 + (uint32_t)((col*4) ^ ((row&7)<<5)));
      float2 ov; ov.x = xv.x + sc*acc[mt][nt][0]; ov.y = xv.y + sc*acc[mt][nt][1];
      *(float2*)(ob + (size_t)row*HWD + col) = ov;
      int row2 = row + 8;
      uint32_t xo2 = (row2 < 40) ? (uint32_t)(STG + row2*512)
                   : (row2 < 80) ? (uint32_t)(2*STG + (row2-40)*512)
                                 : (uint32_t)(3*STG + (row2-80)*512);
      float2 xv2 = *(const float2*)(sm + xo2 + (uint32_t)((col*4) ^ ((row2&7)<<5)));
      float2 ov2; ov2.x = xv2.x + sc*acc[mt][nt][2]; ov2.y = xv2.y + sc*acc[mt][nt][3];
      *(float2*)(ob + (size_t)row2*HWD + col) = ov2;
    }
  }
}

extern "C" void kernel_launch(void* const* d_in, const int* in_sizes, int n_in,
                              void* d_out, int out_size) {
  const float* x     = (const float*)d_in[0];
  const float* w1    = (const float*)d_in[1];
  const float* b1    = (const float*)d_in[2];
  const float* w2    = (const float*)d_in[3];
  const float* b2    = (const float*)d_in[4];
  const float* scale = (const float*)d_in[5];
  float* out = (float*)d_out;

  cudaFuncSetAttribute(k_sinkhorn, cudaFuncAttributeMaxDynamicSharedMemorySize, SMEM_SINK);
  cudaFuncSetAttribute(k_mix, cudaFuncAttributeMaxDynamicSharedMemorySize, SMEM_MIX);

  dim3 gpool(HWD/64, BB);
  k_poolT<<<gpool, 256>>>(x);
  k_fc1<<<BB, RR>>>(w1, b1);
  dim3 gfc2(CC, 2);
  k_fc2_exp<<<gfc2, 256>>>(w2, b2);
  k_sinkhorn<<<BB, 1024, SMEM_SINK>>>();
  dim3 gmix(CC/128, HWD/128, BB);
  k_mix<<<gmix, 256, SMEM_MIX>>>(x, scale, out);
}

// round 17
// speedup vs baseline: 1.3630x; 1.0102x over previous
#include <cuda_runtime.h>
#include <cuda_bf16.h>
#include <cstdint>
#include <cstddef>

#define BB 32
#define CC 256
#define HWD 4096
#define RR 64
#define SINK_IT 4

__device__ float g_pooled[BB*CC];
__device__ float g_h[BB*RR];
__device__ __nv_bfloat16 g_K0[(size_t)BB*CC*CC];
__device__ uint8_t g_M8[(size_t)BB*CC*CC];        // e4m3, M*64
__device__ uint8_t g_x8[(size_t)BB*HWD*CC];       // e4m3 x^T

__device__ __forceinline__ uint32_t s2u(const void* p) {
  return (uint32_t)__cvta_generic_to_shared(p);
}
__device__ __forceinline__ void cp16(uint32_t d, const void* s) {
  asm volatile("cp.async.cg.shared.global [%0], [%1], 16;" :: "r"(d), "l"(s));
}
__device__ __forceinline__ uint32_t fp8x2(float lo, float hi) {
  uint16_t r;
  asm("cvt.rn.satfinite.e4m3x2.f32 %0, %1, %2;" : "=h"(r) : "f"(hi), "f"(lo));
  return (uint32_t)r;
}

// ============ K1: transpose x -> e4m3 x8, partial pooled sums ============
__global__ void __launch_bounds__(256) k_poolT(const float* __restrict__ x) {
  __shared__ float ts[64*68];
  const int b = blockIdx.y, n0 = blockIdx.x * 64, t = threadIdx.x;
  const int rl = t >> 2, c4 = t & 3;
  const int nw = t & 63, cw = (t >> 6) * 16;
  for (int cg = 0; cg < 4; cg++) {
    int ch = cg*64 + rl;
    const float4* src = (const float4*)(x + ((size_t)b*CC + ch)*HWD + n0 + c4*16);
    float4 a = src[0], bq = src[1], cq = src[2], dq = src[3];
    float4* tr = (float4*)(ts + rl*68 + c4*16);
    tr[0]=a; tr[1]=bq; tr[2]=cq; tr[3]=dq;
    float s = (a.x+a.y+a.z+a.w) + (bq.x+bq.y+bq.z+bq.w)
            + (cq.x+cq.y+cq.z+cq.w) + (dq.x+dq.y+dq.z+dq.w);
    s += __shfl_xor_sync(0xffffffffu, s, 1);
    s += __shfl_xor_sync(0xffffffffu, s, 2);
    if (c4 == 0) atomicAdd(&g_pooled[b*CC + ch], s);
    __syncthreads();
    uint32_t pk[4];
    #pragma unroll
    for (int i = 0; i < 4; i++) {
      float v0 = ts[(cw + 4*i + 0)*68 + nw];
      float v1 = ts[(cw + 4*i + 1)*68 + nw];
      float v2 = ts[(cw + 4*i + 2)*68 + nw];
      float v3 = ts[(cw + 4*i + 3)*68 + nw];
      pk[i] = fp8x2(v0, v1) | (fp8x2(v2, v3) << 16);
    }
    uint8_t* dst = g_x8 + ((size_t)b*HWD + n0 + nw)*CC + cg*64 + cw;
    *(uint4*)dst = make_uint4(pk[0], pk[1], pk[2], pk[3]);
    __syncthreads();
  }
}

// ============ K2: h = silu(mean @ w1^T + b1); zero pooled for next replay ===
__global__ void k_fc1(const float* __restrict__ w1, const float* __restrict__ b1) {
  int b = blockIdx.x, r = threadIdx.x;
  __shared__ float p[CC];
  for (int k = r; k < CC; k += RR) p[k] = g_pooled[b*CC + k] * (1.0f/4096.0f);
  __syncthreads();
  for (int k = r; k < CC; k += RR) g_pooled[b*CC + k] = 0.f;
  const float4* wr = (const float4*)(w1 + (size_t)r * CC);
  float acc = b1[r];
  #pragma unroll 8
  for (int k = 0; k < 64; k++) {
    float4 w = wr[k];
    acc += w.x*p[4*k] + w.y*p[4*k+1] + w.z*p[4*k+2] + w.w*p[4*k+3];
  }
  g_h[b*RR + r] = acc / (1.0f + __expf(-acc));
}

// ============ K3: weights -> exp(w - rowmax) -> K0; 16 batches/block ========
__global__ void __launch_bounds__(256) k_fc2_exp(const float* __restrict__ w2,
                                                 const float* __restrict__ b2) {
  const int i = blockIdx.x, j = threadIdx.x;
  const int b0 = blockIdx.y * 16;
  const int w = j >> 5, l = j & 31;
  __shared__ float hs[16*RR];
  __shared__ float red[8*16];
  for (int tt = j; tt < 16*RR; tt += 256) hs[tt] = g_h[b0*RR + tt];
  __syncthreads();

  const float4* w2r = (const float4*)(w2 + (size_t)(i*CC + j) * RR);
  const float bv = b2[i*CC + j];
  float acc[16];
  #pragma unroll
  for (int b = 0; b < 16; b++) acc[b] = bv;
  #pragma unroll
  for (int k4 = 0; k4 < 16; k4++) {
    float4 wv = w2r[k4];
    #pragma unroll
    for (int b = 0; b < 16; b++) {
      float4 hv = *(const float4*)(hs + b*64 + k4*4);
      acc[b] += wv.x*hv.x + wv.y*hv.y + wv.z*hv.z + wv.w*hv.w;
    }
  }
  #pragma unroll
  for (int b = 0; b < 16; b++) {
    float m = acc[b];
    #pragma unroll
    for (int o = 16; o; o >>= 1) m = fmaxf(m, __shfl_xor_sync(0xffffffffu, m, o));
    if (l == b) red[w*16 + b] = m;
  }
  __syncthreads();
  #pragma unroll
  for (int b = 0; b < 16; b++) {
    float bm = red[b];
    #pragma unroll
    for (int ww = 1; ww < 8; ww++) bm = fmaxf(bm, red[ww*16 + b]);
    float e = __expf(acc[b] - bm);
    float eo = __shfl_down_sync(0xffffffffu, e, 1);
    if ((j & 1) == 0) {
      __nv_bfloat162 pk;
      pk.x = __float2bfloat16(e); pk.y = __float2bfloat16(eo);
      *(__nv_bfloat162*)(g_K0 + ((size_t)((b0 + b)*CC + i))*CC + j) = pk;
    }
  }
}

// ============ K4: Sinkhorn u/v scaling form, HFMA2, 4 iters ============
#define KP 264
#define SMEM_SINK (256*KP*2 + 8*256*4 + 256*4 + 256*4 + 256*4 + 128*4)
__global__ void __launch_bounds__(1024, 1) k_sinkhorn() {
  extern __shared__ char smC[];
  __nv_bfloat16* Kb = (__nv_bfloat16*)smC;
  float* red = (float*)(smC + 256*KP*2);
  float* u = red + 8*256;
  float* v = u + 256;
  uint32_t* ub2 = (uint32_t*)(v + 256);
  uint32_t* vb2 = ub2 + 256;
  const int b = blockIdx.x, t = threadIdx.x;
  const __nv_bfloat16* src = g_K0 + (size_t)b * (CC*CC);
  #pragma unroll
  for (int i = 0; i < 8; i++) {
    int idx = t + 1024*i;
    int r = idx >> 5, c8 = idx & 31;
    float4 d = *(const float4*)(src + r*CC + c8*8);
    *(float4*)(Kb + r*KP + c8*8) = d;
  }
  if (t < 256) v[t] = 1.0f;
  if (t < 128) vb2[t] = 0x3F803F80u;
  __syncthreads();

  const int rr = t & 255, q = t >> 8;
  const int cp_ = t & 127, rg = t >> 7;
  const __nv_bfloat162 z2 = __floats2bfloat162_rn(0.f, 0.f);

  for (int it = 0; it < SINK_IT; it++) {
    {
      __nv_bfloat162 a8[8];
      #pragma unroll
      for (int a = 0; a < 8; a++) a8[a] = z2;
      const uint4* kp4 = (const uint4*)(Kb + rr*KP + q*64);
      const uint4* vp4 = (const uint4*)(vb2 + q*32);
      #pragma unroll
      for (int i = 0; i < 8; i++) {
        uint4 kk = kp4[i]; uint4 vv = vp4[i];
        const uint32_t* kw = &kk.x; const uint32_t* vw = &vv.x;
        #pragma unroll
        for (int j = 0; j < 4; j++) {
          a8[(i&1)*4+j] = __hfma2(*(const __nv_bfloat162*)&kw[j],
                                  *(const __nv_bfloat162*)&vw[j], a8[(i&1)*4+j]);
        }
      }
      float s = 0.f;
      #pragma unroll
      for (int a = 0; a < 8; a++) {
        float2 f = __bfloat1622float2(a8[a]);
        s += f.x + f.y;
      }
      red[q*256 + rr] = s;
    }
    __syncthreads();
    if (t < 256) {
      float s = red[t] + red[256+t] + red[512+t] + red[768+t];
      float uu = 1.0f / (s + 1e-12f);
      u[t] = uu;
      __nv_bfloat16 ub = __float2bfloat16(uu);
      __nv_bfloat162 up; up.x = ub; up.y = ub;
      ub2[t] = *(uint32_t*)&up;
    }
    __syncthreads();
    {
      __nv_bfloat162 a8[8];
      #pragma unroll
      for (int a = 0; a < 8; a++) a8[a] = z2;
      const __nv_bfloat16* base = Kb + (rg*32)*KP + 2*cp_;
      const uint32_t* up = ub2 + rg*32;
      #pragma unroll
      for (int i = 0; i < 32; i++) {
        uint32_t k2 = *(const uint32_t*)(base + i*KP);
        uint32_t uu = up[i];
        a8[i&7] = __hfma2(*(const __nv_bfloat162*)&k2,
                          *(const __nv_bfloat162*)&uu, a8[i&7]);
      }
      float a0 = 0.f, a1 = 0.f;
      #pragma unroll
      for (int a = 0; a < 8; a++) {
        float2 f = __bfloat1622float2(a8[a]);
        a0 += f.x; a1 += f.y;
      }
      float2 w2v; w2v.x = a0; w2v.y = a1;
      *(float2*)(red + rg*256 + 2*cp_) = w2v;
    }
    __syncthreads();
    if (t < 256) {
      float s = 0.f;
      #pragma unroll
      for (int g = 0; g < 8; g++) s += red[g*256 + t];
      float vv = 1.0f / (s + 1e-12f);
      v[t] = vv;
      float vn = __shfl_xor_sync(0xffffffffu, vv, 1);
      if ((t & 1) == 0) {
        __nv_bfloat162 vp; vp.x = __float2bfloat16(vv); vp.y = __float2bfloat16(vn);
        vb2[t >> 1] = *(uint32_t*)&vp;
      }
    }
    __syncthreads();
  }
  for (int idx = t; idx < 16384; idx += 1024) {
    int i = idx >> 6, c4 = idx & 63;
    float su = 64.0f * u[i];
    const __nv_bfloat16* rp = Kb + i*KP + 4*c4;
    float m0 = su * __bfloat162float(rp[0]) * v[4*c4+0];
    float m1 = su * __bfloat162float(rp[1]) * v[4*c4+1];
    float m2 = su * __bfloat162float(rp[2]) * v[4*c4+2];
    float m3 = su * __bfloat162float(rp[3]) * v[4*c4+3];
    uint32_t pk = fp8x2(m0, m1) | (fp8x2(m2, m3) << 16);
    *(uint32_t*)(g_M8 + (size_t)b*(CC*CC) + i*CC + 4*c4) = pk;
  }
}

// ===== K5: out = x + (scale/64)*M8@x8^T — 3-stage pipe + smem x residual ====
#define APITCH 80
#define ASTG (128*APITCH)
#define STG (2*ASTG)
#define XPAD (48*512)
#define SMEM_MIX (3*STG + XPAD)
__global__ void __launch_bounds__(256, 2) k_mix(const float* __restrict__ x,
                                                const float* __restrict__ scale,
                                                float* __restrict__ out) {
  extern __shared__ __align__(128) char sm[];
  const int t = threadIdx.x;
  const int m0 = blockIdx.x * 128;
  const int n0 = blockIdx.y * 128;
  const int b  = blockIdx.z;
  const uint32_t s0 = s2u(sm);
  const int w = t >> 5, l = t & 31;
  const int wm = (w & 1) * 64, wn = (w >> 1) * 32;
  const int g = l >> 3, r = l & 7;
  const int lrow = r + (g & 1) * 8;
  const int lchunk = (g >> 1) * 16;

  const uint8_t* Ab = g_M8 + ((size_t)b << 16) + (size_t)m0 * CC;
  const uint8_t* Bb = g_x8 + ((size_t)b << 20) + (size_t)n0 * CC;
  const float* xsrc = x + ((size_t)b*CC + m0)*HWD + n0;

  #define PREFETCH(kc) {                                                        \
    uint32_t As_ = s0 + ((kc) % 3) * STG;                                       \
    uint32_t Bs_ = As_ + ASTG;                                                  \
    _Pragma("unroll")                                                           \
    for (int i_ = 0; i_ < 2; i_++) {                                            \
      int idx = t + 256*i_; int rw = idx >> 2, c_ = idx & 3;                    \
      cp16(As_ + rw*APITCH + c_*16, Ab + (size_t)rw*CC + (kc)*64 + c_*16);      \
      cp16(Bs_ + rw*APITCH + c_*16, Bb + (size_t)rw*CC + (kc)*64 + c_*16);      \
    }                                                                           \
    asm volatile("cp.async.commit_group;");                                     \
  }
  #define XLD(base, r0, cnt) {                                                  \
    _Pragma("unroll")                                                           \
    for (int i_ = 0; i_ < (cnt); i_++) {                                        \
      int idx = t + 256*i_; int rr_ = (idx >> 5), c16 = idx & 31;               \
      int rg_ = (r0) + rr_;                                                     \
      cp16(s0 + (base) + (uint32_t)rr_*512 + (uint32_t)((c16*16) ^ ((rg_&7)<<5)),\
           xsrc + (size_t)rg_*HWD + c16*4);                                     \
    }                                                                           \
    asm volatile("cp.async.commit_group;");                                     \
  }
  #define COMPUTE(kc) {                                                         \
    uint32_t Ast = s0 + ((kc) % 3) * STG;                                       \
    uint32_t Bst = Ast + ASTG;                                                  \
    uint32_t abase = Ast + (uint32_t)(wm + lrow)*APITCH + lchunk;               \
    uint32_t bbase = Bst + (uint32_t)(wn + lrow)*APITCH + lchunk;               \
    _Pragma("unroll")                                                           \
    for (int ks = 0; ks < 2; ks++) {                                            \
      uint32_t bfr[4][2];                                                       \
      _Pragma("unroll")                                                         \
      for (int ng = 0; ng < 2; ng++) {                                          \
        uint32_t r0, r1, r2, r3;                                                \
        asm volatile("ldmatrix.sync.aligned.m8n8.x4.shared.b16 {%0,%1,%2,%3}, [%4];" \
                     : "=r"(r0), "=r"(r1), "=r"(r2), "=r"(r3)                   \
                     : "r"(bbase + ng*16*APITCH + ks*32));                      \
        bfr[2*ng][0]=r0; bfr[2*ng+1][0]=r1; bfr[2*ng][1]=r2; bfr[2*ng+1][1]=r3; \
      }                                                                         \
      _Pragma("unroll")                                                         \
      for (int mt = 0; mt < 4; mt++) {                                          \
        uint32_t a0, a1, a2, a3;                                                \
        asm volatile("ldmatrix.sync.aligned.m8n8.x4.shared.b16 {%0,%1,%2,%3}, [%4];" \
                     : "=r"(a0), "=r"(a1), "=r"(a2), "=r"(a3)                   \
                     : "r"(abase + mt*16*APITCH + ks*32));                      \
        _Pragma("unroll")                                                       \
        for (int nt = 0; nt < 4; nt++) {                                        \
          asm volatile("mma.sync.aligned.m16n8k32.row.col.f32.e4m3.e4m3.f32 "   \
                       "{%0,%1,%2,%3}, {%4,%5,%6,%7}, {%8,%9}, {%0,%1,%2,%3};"  \
                       : "+f"(acc[mt][nt][0]), "+f"(acc[mt][nt][1]),            \
                         "+f"(acc[mt][nt][2]), "+f"(acc[mt][nt][3])             \
                       : "r"(a0), "r"(a1), "r"(a2), "r"(a3),                    \
                         "r"(bfr[nt][0]), "r"(bfr[nt][1]));                     \
        }                                                                       \
      }                                                                         \
    }                                                                           \
  }

  float acc[4][4][4];
  #pragma unroll
  for (int mt = 0; mt < 4; mt++)
    #pragma unroll
    for (int nt = 0; nt < 4; nt++)
      #pragma unroll
      for (int qq = 0; qq < 4; qq++) acc[mt][nt][qq] = 0.f;

  PREFETCH(0)                 // c1
  PREFETCH(1)                 // c2
  XLD(3*STG, 80, 6)           // c3: x rows 80..127 -> pad (always free)

  asm volatile("cp.async.wait_group 2;" ::: "memory");  // c1 done
  __syncthreads();
  PREFETCH(2)                 // c4
  COMPUTE(0)

  asm volatile("cp.async.wait_group 2;" ::: "memory");  // c2 done
  __syncthreads();
  PREFETCH(3)                 // c5
  COMPUTE(1)

  asm volatile("cp.async.wait_group 1;" ::: "memory");  // c4 done
  __syncthreads();
  XLD(STG, 0, 5)              // c6: x rows 0..39 -> stage1 (now free)
  COMPUTE(2)

  asm volatile("cp.async.wait_group 1;" ::: "memory");  // c5 done
  __syncthreads();
  XLD(2*STG, 40, 5)           // c7: x rows 40..79 -> stage2 (now free)
  COMPUTE(3)

  asm volatile("cp.async.wait_group 0;" ::: "memory");  // all x arrived
  __syncthreads();

  const float sc = scale[0] * 0.015625f;
  float* ob = out + ((size_t)b*CC + m0)*HWD + n0;
  const int er = l >> 2, ec = 2 * (l & 3);
  #pragma unroll
  for (int mt = 0; mt < 4; mt++) {
    #pragma unroll
    for (int nt = 0; nt < 4; nt++) {
      int row = wm + mt*16 + er;
      int col = wn + nt*8 + ec;
      uint32_t xo1 = (row < 40) ? (uint32_t)(STG + row*512)
                   : (row < 80) ? (uint32_t)(2*STG + (row-40)*512)
                                : (uint32_t)(3*STG + (row-80)*512);
      float2 xv = *(const float2*)(sm + xo1 + (uint32_t)((col*4) ^ ((row&7)<<5)));
      float2 ov; ov.x = xv.x + sc*acc[mt][nt][0]; ov.y = xv.y + sc*acc[mt][nt][1];
      *(float2*)(ob + (size_t)row*HWD + col) = ov;
      int row2 = row + 8;
      uint32_t xo2 = (row2 < 40) ? (uint32_t)(STG + row2*512)
                   : (row2 < 80) ? (uint32_t)(2*STG + (row2-40)*512)
                                 : (uint32_t)(3*STG + (row2-80)*512);
      float2 xv2 = *(const float2*)(sm + xo2 + (uint32_t)((col*4) ^ ((row2&7)<<5)));
      float2 ov2; ov2.x = xv2.x + sc*acc[mt][nt][2]; ov2.y = xv2.y + sc*acc[mt][nt][3];
      *(float2*)(ob + (size_t)row2*HWD + col) = ov2;
    }
  }
}

extern "C" void kernel_launch(void* const* d_in, const int* in_sizes, int n_in,
                              void* d_out, int out_size) {
  const float* x     = (const float*)d_in[0];
  const float* w1    = (const float*)d_in[1];
  const float* b1    = (const float*)d_in[2];
  const float* w2    = (const float*)d_in[3];
  const float* b2    = (const float*)d_in[4];
  const float* scale = (const float*)d_in[5];
  float* out = (float*)d_out;

  cudaFuncSetAttribute(k_sinkhorn, cudaFuncAttributeMaxDynamicSharedMemorySize, SMEM_SINK);
  cudaFuncSetAttribute(k_mix, cudaFuncAttributeMaxDynamicSharedMemorySize, SMEM_MIX);

  dim3 gpool(HWD/64, BB);
  k_poolT<<<gpool, 256>>>(x);
  k_fc1<<<BB, RR>>>(w1, b1);
  dim3 gfc2(CC, 2);
  k_fc2_exp<<<gfc2, 256>>>(w2, b2);
  k_sinkhorn<<<BB, 1024, SMEM_SINK>>>();
  dim3 gmix(CC/128, HWD/128, BB);
  k_mix<<<gmix, 256, SMEM_MIX>>>(x, scale, out);
}